// round 10
// baseline (speedup 1.0000x reference)
#include <cuda_runtime.h>
#include <math.h>

typedef unsigned long long u64;
typedef unsigned int u32;

#define NWARP 4
#define TLB   8
#define BUF   2208

__device__ __forceinline__ u64 pk2(float a, float b) {
    u64 r; asm("mov.b64 %0, {%1, %2};" : "=l"(r) : "r"(__float_as_uint(a)), "r"(__float_as_uint(b)));
    return r;
}
__device__ __forceinline__ void upk2(u64 v, float& a, float& b) {
    u32 x, y; asm("mov.b64 {%0, %1}, %2;" : "=r"(x), "=r"(y) : "l"(v));
    a = __uint_as_float(x); b = __uint_as_float(y);
}
__device__ __forceinline__ u64 dup2(float a) { return pk2(a, a); }
__device__ __forceinline__ u64 ffma2(u64 a, u64 b, u64 c) {
    u64 d; asm("fma.rn.f32x2 %0, %1, %2, %3;" : "=l"(d) : "l"(a), "l"(b), "l"(c)); return d;
}
__device__ __forceinline__ float2 relu2(u64 v) {
    float a, b; upk2(v, a, b); return make_float2(fmaxf(a, 0.f), fmaxf(b, 0.f));
}
__device__ __forceinline__ ulonglong2 ld128(const float* p) { return *reinterpret_cast<const ulonglong2*>(p); }
__device__ __forceinline__ u64 ld64(const float* p)         { return *reinterpret_cast<const u64*>(p); }
__device__ __forceinline__ float4 ld4(const float* p)       { return *reinterpret_cast<const float4*>(p); }
__device__ __forceinline__ void st4(float* p, float4 v)     { *reinterpret_cast<float4*>(p) = v; }
__device__ __forceinline__ float relu(float x) { return fmaxf(x, 0.f); }

__global__ __launch_bounds__(NWARP * 32)
void policy_kernel(
    const float* __restrict__ queue, const float* __restrict__ waiting,
    const float* __restrict__ phase_onehot, const float* __restrict__ elapsed,
    const int*   __restrict__ region_ids, const float* __restrict__ noise,
    const float* __restrict__ lane_w1, const float* __restrict__ lane_b1,
    const float* __restrict__ lane_w2, const float* __restrict__ lane_b2,
    const float* __restrict__ attn_in_w, const float* __restrict__ attn_in_b,
    const float* __restrict__ attn_out_w, const float* __restrict__ attn_out_b,
    const float* __restrict__ phase_w1, const float* __restrict__ phase_b1,
    const float* __restrict__ phase_w2, const float* __restrict__ phase_b2,
    const float* __restrict__ region_table,
    const float* __restrict__ head_w1, const float* __restrict__ head_b1,
    const float* __restrict__ head_w2, const float* __restrict__ head_b2,
    const float* __restrict__ log_std,
    float* __restrict__ out, int N)
{
    __shared__ float wb[NWARP][BUF];       // per-warp scratch; flat-aliased after S5a
    __shared__ float featp[200][12];       // transposed features [k][row], rows 0..7

    const int tid  = threadIdx.x;
    const int warp = tid >> 5, lane = tid & 31;
    const int n0   = blockIdx.x * TLB + warp * 2;
    float* A = wb[warp];
    float* shp  = &wb[0][0];               // 8832 floats flat
    float* phT  = shp;                     // [128][12]  -> [0,1536)
    float* Pp5  = shp + 1536;              // [4][8][64] -> [1536,3584)
    float* Pp6  = shp + 3584;              // [4][8][128]-> [3584,7680)
    float* Pp8  = shp + 1536;              // [2][8][128] reuse in P4
    float* obarT = &featp[64][0];          // [64][12] in featp rows 64..128 (overwritten later)

    const int rgt = lane >> 4;
    const int jg4 = (lane & 15) * 4;
    const int j4  = lane * 4;

    const int na = min(n0,     N - 1);
    const int nb = min(n0 + 1, N - 1);
    const float ee[2] = { elapsed[na], elapsed[nb] };

    // ---- S1: lane MLP L1 -> h ----
    {
        ulonglong2 W0 = ld128(lane_w1 + j4);
        ulonglong2 W1 = ld128(lane_w1 + 128 + j4);
        ulonglong2 W2 = ld128(lane_w1 + 256 + j4);
        ulonglong2 BB = ld128(lane_b1 + j4);
#pragma unroll
        for (int t = 0; t < 2; t++) {
            const int n = t ? nb : na;
            float4 qv = ld4(queue + 4 * n);
            float4 wv = ld4(waiting + 4 * n);
            u64 ed = dup2(ee[t]);
            float qa[4] = {qv.x, qv.y, qv.z, qv.w};
            float wa[4] = {wv.x, wv.y, wv.z, wv.w};
#pragma unroll
            for (int l = 0; l < 4; l++) {
                u64 qd = dup2(qa[l]), wd = dup2(wa[l]);
                u64 lo = ffma2(qd, W0.x, BB.x); lo = ffma2(wd, W1.x, lo); lo = ffma2(ed, W2.x, lo);
                u64 hi = ffma2(qd, W0.y, BB.y); hi = ffma2(wd, W1.y, hi); hi = ffma2(ed, W2.y, hi);
                float2 r0 = relu2(lo), r1 = relu2(hi);
                st4(A + t * 528 + l * 128 + j4, make_float4(r0.x, r0.y, r1.x, r1.y));
            }
        }
    }
    __syncwarp();

    // ---- S2: lane MLP L2 -> emb ----
    {
        ulonglong2 bb = ld128(lane_b2 + jg4);
        u64 acc[4][2];
#pragma unroll
        for (int l = 0; l < 4; l++) { acc[l][0] = bb.x; acc[l][1] = bb.y; }
#pragma unroll 2
        for (int k = 0; k < 128; k += 4) {
            float hv[4][4];
#pragma unroll
            for (int l = 0; l < 4; l++) {
                float4 v = ld4(A + rgt * 528 + l * 128 + k);
                hv[l][0] = v.x; hv[l][1] = v.y; hv[l][2] = v.z; hv[l][3] = v.w;
            }
#pragma unroll
            for (int kk = 0; kk < 4; kk++) {
                ulonglong2 w = ld128(lane_w2 + (k + kk) * 64 + jg4);
#pragma unroll
                for (int l = 0; l < 4; l++) {
                    u64 d = dup2(hv[l][kk]);
                    acc[l][0] = ffma2(d, w.x, acc[l][0]);
                    acc[l][1] = ffma2(d, w.y, acc[l][1]);
                }
            }
        }
#pragma unroll
        for (int l = 0; l < 4; l++) {
            float2 r0 = relu2(acc[l][0]), r1 = relu2(acc[l][1]);
            st4(A + 1664 + rgt * 272 + l * 64 + jg4, make_float4(r0.x, r0.y, r1.x, r1.y));
        }
    }
    __syncwarp();

    // ---- S3: QKV ----
#pragma unroll
    for (int m = 0; m < 3; m++) {
        ulonglong2 bm = ld128(attn_in_b + 64 * m + jg4);
        u64 acc[4][2];
#pragma unroll
        for (int l = 0; l < 4; l++) { acc[l][0] = bm.x; acc[l][1] = bm.y; }
#pragma unroll 2
        for (int k = 0; k < 64; k += 4) {
            float ev[4][4];
#pragma unroll
            for (int l = 0; l < 4; l++) {
                float4 v = ld4(A + 1664 + rgt * 272 + l * 64 + k);
                ev[l][0] = v.x; ev[l][1] = v.y; ev[l][2] = v.z; ev[l][3] = v.w;
            }
#pragma unroll
            for (int kk = 0; kk < 4; kk++) {
                ulonglong2 w = ld128(attn_in_w + (k + kk) * 192 + 64 * m + jg4);
#pragma unroll
                for (int l = 0; l < 4; l++) {
                    u64 d = dup2(ev[l][kk]);
                    acc[l][0] = ffma2(d, w.x, acc[l][0]);
                    acc[l][1] = ffma2(d, w.y, acc[l][1]);
                }
            }
        }
#pragma unroll
        for (int l = 0; l < 4; l++) {
            float a0, a1, a2, a3; upk2(acc[l][0], a0, a1); upk2(acc[l][1], a2, a3);
            st4(A + rgt * 816 + l * 200 + m * 64 + jg4, make_float4(a0, a1, a2, a3));
        }
    }
    __syncwarp();

    // ---- S4: attention ----
    {
        const int t4 = rgt, r4 = lane & 15, hh = r4 >> 2, ql = r4 & 3;
        const float* qb = A + t4 * 816 + ql * 200 + hh * 16;
        float q[16];
#pragma unroll
        for (int i = 0; i < 4; i++) {
            float4 v = ld4(qb + 4 * i);
            q[4*i] = v.x; q[4*i+1] = v.y; q[4*i+2] = v.z; q[4*i+3] = v.w;
        }
        float sc[4];
#pragma unroll
        for (int kl = 0; kl < 4; kl++) {
            const float* kb = A + t4 * 816 + kl * 200 + 64 + hh * 16;
            float d = 0.f;
#pragma unroll
            for (int i = 0; i < 4; i++) {
                float4 v = ld4(kb + 4 * i);
                d = fmaf(q[4*i], v.x, d); d = fmaf(q[4*i+1], v.y, d);
                d = fmaf(q[4*i+2], v.z, d); d = fmaf(q[4*i+3], v.w, d);
            }
            sc[kl] = d * 0.25f;
        }
        float mx = fmaxf(fmaxf(sc[0], sc[1]), fmaxf(sc[2], sc[3]));
        float es = 0.f;
#pragma unroll
        for (int kl = 0; kl < 4; kl++) { sc[kl] = __expf(sc[kl] - mx); es += sc[kl]; }
        float inv = 1.f / es;
#pragma unroll
        for (int kl = 0; kl < 4; kl++) sc[kl] *= inv;
        float o[16];
#pragma unroll
        for (int i = 0; i < 4; i++) {
            float ox = 0.f, oy = 0.f, oz = 0.f, ow = 0.f;
#pragma unroll
            for (int kl = 0; kl < 4; kl++) {
                float4 v = ld4(A + t4 * 816 + kl * 200 + 128 + hh * 16 + 4 * i);
                ox = fmaf(sc[kl], v.x, ox); oy = fmaf(sc[kl], v.y, oy);
                oz = fmaf(sc[kl], v.z, oz); ow = fmaf(sc[kl], v.w, ow);
            }
            o[4*i] = ox; o[4*i+1] = oy; o[4*i+2] = oz; o[4*i+3] = ow;
        }
        __syncwarp();
#pragma unroll
        for (int i = 0; i < 4; i++)
            st4(A + t4 * 280 + ql * 68 + hh * 16 + 4 * i,
                make_float4(o[4*i], o[4*i+1], o[4*i+2], o[4*i+3]));
    }
    __syncwarp();

    // ---- S5a: obar -> obarT[k][row] (transposed, block-shared) ----
#pragma unroll
    for (int ii = 0; ii < 4; ii++) {
        int i = lane + 32 * ii;
        int t = i >> 6, jj = i & 63;
        float s = A[t*280 + jj] + A[t*280 + 68 + jj] + A[t*280 + 136 + jj] + A[t*280 + 204 + jj];
        obarT[jj * 12 + 2 * warp + t] = 0.25f * s;
    }
    __syncthreads();   // all per-warp A dead from here; shp aliases are safe

    // ==== P1: S5b partial (k-split) + S6L1 (transposed phase hidden) ====
    {
        const int k0 = 16 * warp, j2 = lane * 2;
        u64 acc[8];
#pragma unroll
        for (int r = 0; r < 8; r++) acc[r] = 0ULL;
#pragma unroll 4
        for (int k = k0; k < k0 + 16; k++) {
            u64 wk = ld64(attn_out_w + k * 64 + j2);
            float4 fa = ld4(obarT + k * 12);
            float4 fb = ld4(obarT + k * 12 + 4);
            acc[0] = ffma2(dup2(fa.x), wk, acc[0]); acc[1] = ffma2(dup2(fa.y), wk, acc[1]);
            acc[2] = ffma2(dup2(fa.z), wk, acc[2]); acc[3] = ffma2(dup2(fa.w), wk, acc[3]);
            acc[4] = ffma2(dup2(fb.x), wk, acc[4]); acc[5] = ffma2(dup2(fb.y), wk, acc[5]);
            acc[6] = ffma2(dup2(fb.z), wk, acc[6]); acc[7] = ffma2(dup2(fb.w), wk, acc[7]);
        }
#pragma unroll
        for (int r = 0; r < 8; r++)
            *reinterpret_cast<u64*>(Pp5 + warp * 512 + r * 64 + j2) = acc[r];
    }
    {
        float4 poa = ld4(phase_onehot + 4 * na);
        float4 pob = ld4(phase_onehot + 4 * nb);
        float xa[5] = {poa.x, poa.y, poa.z, poa.w, ee[0]};
        float xb[5] = {pob.x, pob.y, pob.z, pob.w, ee[1]};
#pragma unroll
        for (int i = 0; i < 4; i++) {
            int h1 = lane + 32 * i;
            float b = phase_b1[h1];
            float w0 = phase_w1[h1], w1 = phase_w1[128 + h1], w2 = phase_w1[256 + h1];
            float w3 = phase_w1[384 + h1], w4 = phase_w1[512 + h1];
            float va = b + xa[0]*w0 + xa[1]*w1 + xa[2]*w2 + xa[3]*w3 + xa[4]*w4;
            float vb = b + xb[0]*w0 + xb[1]*w1 + xb[2]*w2 + xb[3]*w3 + xb[4]*w4;
            phT[h1 * 12 + 2 * warp + 0] = relu(va);
            phT[h1 * 12 + 2 * warp + 1] = relu(vb);
        }
    }
    __syncthreads();

    // ==== P2: S5b final -> featp[0:64) ; S6L2 partial (k-split) ====
    {
        const int j2 = lane * 2;
        float2 b = *reinterpret_cast<const float2*>(attn_out_b + j2);
#pragma unroll
        for (int tt = 0; tt < 2; tt++) {
            const int r = 2 * warp + tt;
            float c0 = b.x, c1 = b.y;
#pragma unroll
            for (int q = 0; q < 4; q++) {
                float2 v = *reinterpret_cast<const float2*>(Pp5 + q * 512 + r * 64 + j2);
                c0 += v.x; c1 += v.y;
            }
            featp[j2][r] = c0; featp[j2 + 1][r] = c1;
        }
    }
    {
        const int k0 = 32 * warp;
        u64 acc[8][2];
#pragma unroll
        for (int r = 0; r < 8; r++) acc[r][0] = acc[r][1] = 0ULL;
#pragma unroll 2
        for (int k = k0; k < k0 + 32; k++) {
            ulonglong2 w = ld128(phase_w2 + k * 128 + j4);
            float4 fa = ld4(phT + k * 12);
            float4 fb = ld4(phT + k * 12 + 4);
            float f[8] = {fa.x, fa.y, fa.z, fa.w, fb.x, fb.y, fb.z, fb.w};
#pragma unroll
            for (int r = 0; r < 8; r++) {
                u64 d = dup2(f[r]);
                acc[r][0] = ffma2(d, w.x, acc[r][0]);
                acc[r][1] = ffma2(d, w.y, acc[r][1]);
            }
        }
#pragma unroll
        for (int r = 0; r < 8; r++) {
            float a0, a1, a2, a3; upk2(acc[r][0], a0, a1); upk2(acc[r][1], a2, a3);
            st4(Pp6 + warp * 1024 + r * 128 + j4, make_float4(a0, a1, a2, a3));
        }
    }
    __syncthreads();

    // ==== P3: S6 final -> featp[64:192) ; S7 region -> featp[192:200) ====
    {
        float4 b2 = ld4(phase_b2 + j4);
#pragma unroll
        for (int tt = 0; tt < 2; tt++) {
            const int r = 2 * warp + tt;
            float4 p0 = ld4(Pp6 + r * 128 + j4);
            float4 p1 = ld4(Pp6 + 1024 + r * 128 + j4);
            float4 p2 = ld4(Pp6 + 2048 + r * 128 + j4);
            float4 p3 = ld4(Pp6 + 3072 + r * 128 + j4);
            featp[64 + j4 + 0][r] = relu(p0.x + p1.x + p2.x + p3.x + b2.x);
            featp[64 + j4 + 1][r] = relu(p0.y + p1.y + p2.y + p3.y + b2.y);
            featp[64 + j4 + 2][r] = relu(p0.z + p1.z + p2.z + p3.z + b2.z);
            featp[64 + j4 + 3][r] = relu(p0.w + p1.w + p2.w + p3.w + b2.w);
        }
    }
    if (lane < 16) {
        const int t = lane >> 3, f = lane & 7;
        const int n = t ? nb : na;
        int rid = region_ids[n];
        rid = min(max(rid, 0), 3);
        featp[192 + f][warp * 2 + t] = region_table[rid * 8 + f];
    }
    __syncthreads();

    // ==== P4: S8 partial — warp = (k-half, j-half) ====
    {
        const int kh = warp & 1, jh = warp >> 1;
        const int j2 = jh * 64 + lane * 2;
        const int k0 = kh * 100;
        u64 acc[8];
#pragma unroll
        for (int r = 0; r < 8; r++) acc[r] = 0ULL;
#pragma unroll 4
        for (int k = k0; k < k0 + 100; k++) {
            u64 wk = ld64(head_w1 + k * 128 + j2);
            float4 fa = ld4(&featp[k][0]);
            float4 fb = ld4(&featp[k][4]);
            acc[0] = ffma2(dup2(fa.x), wk, acc[0]); acc[1] = ffma2(dup2(fa.y), wk, acc[1]);
            acc[2] = ffma2(dup2(fa.z), wk, acc[2]); acc[3] = ffma2(dup2(fa.w), wk, acc[3]);
            acc[4] = ffma2(dup2(fb.x), wk, acc[4]); acc[5] = ffma2(dup2(fb.y), wk, acc[5]);
            acc[6] = ffma2(dup2(fb.z), wk, acc[6]); acc[7] = ffma2(dup2(fb.w), wk, acc[7]);
        }
#pragma unroll
        for (int r = 0; r < 8; r++)
            *reinterpret_cast<u64*>(Pp8 + kh * 1024 + r * 128 + j2) = acc[r];
    }
    __syncthreads();

    // ==== P5: S8 final — warp combines its own 2 rows, writes outputs ====
    {
        float4 b  = ld4(head_b1 + j4);
        float4 w2 = ld4(head_w2 + j4);
        float sums[2];
#pragma unroll
        for (int tt = 0; tt < 2; tt++) {
            const int r = 2 * warp + tt;
            float4 p0 = ld4(Pp8 + r * 128 + j4);
            float4 p1 = ld4(Pp8 + 1024 + r * 128 + j4);
            float a0 = relu(p0.x + p1.x + b.x);
            float a1 = relu(p0.y + p1.y + b.y);
            float a2 = relu(p0.z + p1.z + b.z);
            float a3 = relu(p0.w + p1.w + b.w);
            float s = a0 * w2.x + a1 * w2.y + a2 * w2.z + a3 * w2.w;
#pragma unroll
            for (int off = 16; off > 0; off >>= 1)
                s += __shfl_xor_sync(0xffffffffu, s, off);
            sums[tt] = s;
        }
        if (lane == 0) {
            float ls = log_std[0];
            float sd = expf(ls);
            float bb2 = head_b2[0];
#pragma unroll
            for (int tt = 0; tt < 2; tt++) {
                const int n = n0 + tt;
                if (n < N) {
                    float mean = sums[tt] + bb2;
                    float nz = noise[n];
                    float act = mean + sd * nz;
                    out[n] = fminf(fmaxf(act, -1.0f), 1.0f);
                    out[N + n] = -0.5f * (nz * nz + 2.0f * ls + 1.8378770664093454f);
                }
            }
        }
    }
}

extern "C" void kernel_launch(void* const* d_in, const int* in_sizes, int n_in,
                              void* d_out, int out_size)
{
    const float* queue        = (const float*)d_in[0];
    const float* waiting      = (const float*)d_in[1];
    const float* phase_onehot = (const float*)d_in[2];
    const float* elapsed      = (const float*)d_in[3];
    const int*   region_ids   = (const int*)  d_in[4];
    const float* noise        = (const float*)d_in[5];
    const float* lane_w1      = (const float*)d_in[6];
    const float* lane_b1      = (const float*)d_in[7];
    const float* lane_w2      = (const float*)d_in[8];
    const float* lane_b2      = (const float*)d_in[9];
    const float* attn_in_w    = (const float*)d_in[10];
    const float* attn_in_b    = (const float*)d_in[11];
    const float* attn_out_w   = (const float*)d_in[12];
    const float* attn_out_b   = (const float*)d_in[13];
    const float* phase_w1     = (const float*)d_in[14];
    const float* phase_b1     = (const float*)d_in[15];
    const float* phase_w2     = (const float*)d_in[16];
    const float* phase_b2     = (const float*)d_in[17];
    const float* region_table = (const float*)d_in[18];
    const float* head_w1      = (const float*)d_in[19];
    const float* head_b1      = (const float*)d_in[20];
    const float* head_w2      = (const float*)d_in[21];
    const float* head_b2      = (const float*)d_in[22];
    const float* log_std      = (const float*)d_in[23];

    const int N = in_sizes[3];
    float* out = (float*)d_out;

    int blocks = (N + TLB - 1) / TLB;
    policy_kernel<<<blocks, NWARP * 32>>>(
        queue, waiting, phase_onehot, elapsed, region_ids, noise,
        lane_w1, lane_b1, lane_w2, lane_b2,
        attn_in_w, attn_in_b, attn_out_w, attn_out_b,
        phase_w1, phase_b1, phase_w2, phase_b2,
        region_table, head_w1, head_b1, head_w2, head_b2, log_std,
        out, N);
}

// round 11
// speedup vs baseline: 1.5544x; 1.5544x over previous
#include <cuda_runtime.h>
#include <math.h>

typedef unsigned long long u64;
typedef unsigned int u32;

#define NWARP 4
#define TLB   8
#define BUF   2208

__device__ __forceinline__ u64 pk2(float a, float b) {
    u64 r; asm("mov.b64 %0, {%1, %2};" : "=l"(r) : "r"(__float_as_uint(a)), "r"(__float_as_uint(b)));
    return r;
}
__device__ __forceinline__ void upk2(u64 v, float& a, float& b) {
    u32 x, y; asm("mov.b64 {%0, %1}, %2;" : "=r"(x), "=r"(y) : "l"(v));
    a = __uint_as_float(x); b = __uint_as_float(y);
}
__device__ __forceinline__ u64 dup2(float a) { return pk2(a, a); }
__device__ __forceinline__ u64 ffma2(u64 a, u64 b, u64 c) {
    u64 d; asm("fma.rn.f32x2 %0, %1, %2, %3;" : "=l"(d) : "l"(a), "l"(b), "l"(c)); return d;
}
__device__ __forceinline__ float2 relu2(u64 v) {
    float a, b; upk2(v, a, b); return make_float2(fmaxf(a, 0.f), fmaxf(b, 0.f));
}
__device__ __forceinline__ ulonglong2 ld128(const float* p) { return *reinterpret_cast<const ulonglong2*>(p); }
__device__ __forceinline__ u64 ld64(const float* p)         { return *reinterpret_cast<const u64*>(p); }
__device__ __forceinline__ float4 ld4(const float* p)       { return *reinterpret_cast<const float4*>(p); }
__device__ __forceinline__ void st4(float* p, float4 v)     { *reinterpret_cast<float4*>(p) = v; }
__device__ __forceinline__ float relu(float x) { return fmaxf(x, 0.f); }

__global__ __launch_bounds__(NWARP * 32)
void policy_kernel(
    const float* __restrict__ queue, const float* __restrict__ waiting,
    const float* __restrict__ phase_onehot, const float* __restrict__ elapsed,
    const int*   __restrict__ region_ids, const float* __restrict__ noise,
    const float* __restrict__ lane_w1, const float* __restrict__ lane_b1,
    const float* __restrict__ lane_w2, const float* __restrict__ lane_b2,
    const float* __restrict__ attn_in_w, const float* __restrict__ attn_in_b,
    const float* __restrict__ attn_out_w, const float* __restrict__ attn_out_b,
    const float* __restrict__ phase_w1, const float* __restrict__ phase_b1,
    const float* __restrict__ phase_w2, const float* __restrict__ phase_b2,
    const float* __restrict__ region_table,
    const float* __restrict__ head_w1, const float* __restrict__ head_b1,
    const float* __restrict__ head_w2, const float* __restrict__ head_b2,
    const float* __restrict__ log_std,
    float* __restrict__ out, int N)
{
    __shared__ float wb[NWARP][BUF];
    __shared__ float featp[200][12];

    const int tid  = threadIdx.x;
    const int warp = tid >> 5, lane = tid & 31;
    const int n0   = blockIdx.x * TLB + warp * 2;
    float* A    = wb[warp];
    float* phS  = &wb[0][0];
    float* Pp0  = &wb[1][0];
    float* Pp1  = &wb[2][0];
    float* Pp8a = &wb[1][0];   // S8 partials, k-half 0 (wb[1] dead after S6-final)
    float* Pp8b = &wb[2][0];   // S8 partials, k-half 1

    const int rgt = lane >> 4;
    const int jg4 = (lane & 15) * 4;
    const int j4  = lane * 4;

    const int na = min(n0,     N - 1);
    const int nb = min(n0 + 1, N - 1);
    const float ee[2] = { elapsed[na], elapsed[nb] };

    // ---- S1: lane MLP L1 -> h ----
    {
        ulonglong2 W0 = ld128(lane_w1 + j4);
        ulonglong2 W1 = ld128(lane_w1 + 128 + j4);
        ulonglong2 W2 = ld128(lane_w1 + 256 + j4);
        ulonglong2 BB = ld128(lane_b1 + j4);
#pragma unroll
        for (int t = 0; t < 2; t++) {
            const int n = t ? nb : na;
            float4 qv = ld4(queue + 4 * n);
            float4 wv = ld4(waiting + 4 * n);
            u64 ed = dup2(ee[t]);
            float qa[4] = {qv.x, qv.y, qv.z, qv.w};
            float wa[4] = {wv.x, wv.y, wv.z, wv.w};
#pragma unroll
            for (int l = 0; l < 4; l++) {
                u64 qd = dup2(qa[l]), wd = dup2(wa[l]);
                u64 lo = ffma2(qd, W0.x, BB.x); lo = ffma2(wd, W1.x, lo); lo = ffma2(ed, W2.x, lo);
                u64 hi = ffma2(qd, W0.y, BB.y); hi = ffma2(wd, W1.y, hi); hi = ffma2(ed, W2.y, hi);
                float2 r0 = relu2(lo), r1 = relu2(hi);
                st4(A + t * 528 + l * 128 + j4, make_float4(r0.x, r0.y, r1.x, r1.y));
            }
        }
    }
    __syncwarp();

    // ---- S2: lane MLP L2 -> emb ----
    {
        ulonglong2 bb = ld128(lane_b2 + jg4);
        u64 acc[4][2];
#pragma unroll
        for (int l = 0; l < 4; l++) { acc[l][0] = bb.x; acc[l][1] = bb.y; }
#pragma unroll 2
        for (int k = 0; k < 128; k += 4) {
            float hv[4][4];
#pragma unroll
            for (int l = 0; l < 4; l++) {
                float4 v = ld4(A + rgt * 528 + l * 128 + k);
                hv[l][0] = v.x; hv[l][1] = v.y; hv[l][2] = v.z; hv[l][3] = v.w;
            }
#pragma unroll
            for (int kk = 0; kk < 4; kk++) {
                ulonglong2 w = ld128(lane_w2 + (k + kk) * 64 + jg4);
#pragma unroll
                for (int l = 0; l < 4; l++) {
                    u64 d = dup2(hv[l][kk]);
                    acc[l][0] = ffma2(d, w.x, acc[l][0]);
                    acc[l][1] = ffma2(d, w.y, acc[l][1]);
                }
            }
        }
#pragma unroll
        for (int l = 0; l < 4; l++) {
            float2 r0 = relu2(acc[l][0]), r1 = relu2(acc[l][1]);
            st4(A + 1664 + rgt * 272 + l * 64 + jg4, make_float4(r0.x, r0.y, r1.x, r1.y));
        }
    }
    __syncwarp();

    // ---- S3: QKV ----
#pragma unroll
    for (int m = 0; m < 3; m++) {
        ulonglong2 bm = ld128(attn_in_b + 64 * m + jg4);
        u64 acc[4][2];
#pragma unroll
        for (int l = 0; l < 4; l++) { acc[l][0] = bm.x; acc[l][1] = bm.y; }
#pragma unroll 2
        for (int k = 0; k < 64; k += 4) {
            float ev[4][4];
#pragma unroll
            for (int l = 0; l < 4; l++) {
                float4 v = ld4(A + 1664 + rgt * 272 + l * 64 + k);
                ev[l][0] = v.x; ev[l][1] = v.y; ev[l][2] = v.z; ev[l][3] = v.w;
            }
#pragma unroll
            for (int kk = 0; kk < 4; kk++) {
                ulonglong2 w = ld128(attn_in_w + (k + kk) * 192 + 64 * m + jg4);
#pragma unroll
                for (int l = 0; l < 4; l++) {
                    u64 d = dup2(ev[l][kk]);
                    acc[l][0] = ffma2(d, w.x, acc[l][0]);
                    acc[l][1] = ffma2(d, w.y, acc[l][1]);
                }
            }
        }
#pragma unroll
        for (int l = 0; l < 4; l++) {
            float a0, a1, a2, a3; upk2(acc[l][0], a0, a1); upk2(acc[l][1], a2, a3);
            st4(A + rgt * 816 + l * 200 + m * 64 + jg4, make_float4(a0, a1, a2, a3));
        }
    }
    __syncwarp();

    // ---- S4: attention ----
    {
        const int t4 = rgt, r4 = lane & 15, hh = r4 >> 2, ql = r4 & 3;
        const float* qb = A + t4 * 816 + ql * 200 + hh * 16;
        float q[16];
#pragma unroll
        for (int i = 0; i < 4; i++) {
            float4 v = ld4(qb + 4 * i);
            q[4*i] = v.x; q[4*i+1] = v.y; q[4*i+2] = v.z; q[4*i+3] = v.w;
        }
        float sc[4];
#pragma unroll
        for (int kl = 0; kl < 4; kl++) {
            const float* kb = A + t4 * 816 + kl * 200 + 64 + hh * 16;
            float d = 0.f;
#pragma unroll
            for (int i = 0; i < 4; i++) {
                float4 v = ld4(kb + 4 * i);
                d = fmaf(q[4*i], v.x, d); d = fmaf(q[4*i+1], v.y, d);
                d = fmaf(q[4*i+2], v.z, d); d = fmaf(q[4*i+3], v.w, d);
            }
            sc[kl] = d * 0.25f;
        }
        float mx = fmaxf(fmaxf(sc[0], sc[1]), fmaxf(sc[2], sc[3]));
        float es = 0.f;
#pragma unroll
        for (int kl = 0; kl < 4; kl++) { sc[kl] = __expf(sc[kl] - mx); es += sc[kl]; }
        float inv = 1.f / es;
#pragma unroll
        for (int kl = 0; kl < 4; kl++) sc[kl] *= inv;
        float o[16];
#pragma unroll
        for (int i = 0; i < 4; i++) {
            float ox = 0.f, oy = 0.f, oz = 0.f, ow = 0.f;
#pragma unroll
            for (int kl = 0; kl < 4; kl++) {
                float4 v = ld4(A + t4 * 816 + kl * 200 + 128 + hh * 16 + 4 * i);
                ox = fmaf(sc[kl], v.x, ox); oy = fmaf(sc[kl], v.y, oy);
                oz = fmaf(sc[kl], v.z, oz); ow = fmaf(sc[kl], v.w, ow);
            }
            o[4*i] = ox; o[4*i+1] = oy; o[4*i+2] = oz; o[4*i+3] = ow;
        }
        __syncwarp();
#pragma unroll
        for (int i = 0; i < 4; i++)
            st4(A + t4 * 280 + ql * 68 + hh * 16 + 4 * i,
                make_float4(o[4*i], o[4*i+1], o[4*i+2], o[4*i+3]));
    }
    __syncwarp();

    // ---- S5a: obar ----
#pragma unroll
    for (int ii = 0; ii < 4; ii++) {
        int i = lane + 32 * ii;
        int t = i >> 6, jj = i & 63;
        float s = A[t*280 + jj] + A[t*280 + 68 + jj] + A[t*280 + 136 + jj] + A[t*280 + 204 + jj];
        A[1088 + t * 80 + jj] = 0.25f * s;
    }
    __syncthreads();

    // ---- S5b: ctx -> featp[0:64) ----
    {
        ulonglong2 ob = ld128(attn_out_b + jg4);
        u64 a0 = ob.x, a1 = ob.y;
#pragma unroll 2
        for (int k = 0; k < 64; k += 4) {
            float4 v = ld4(A + 1088 + rgt * 80 + k);
            float ov[4] = {v.x, v.y, v.z, v.w};
#pragma unroll
            for (int kk = 0; kk < 4; kk++) {
                ulonglong2 w = ld128(attn_out_w + (k + kk) * 64 + jg4);
                u64 d = dup2(ov[kk]);
                a0 = ffma2(d, w.x, a0);
                a1 = ffma2(d, w.y, a1);
            }
        }
        const int row = warp * 2 + rgt;
        float c0, c1, c2, c3; upk2(a0, c0, c1); upk2(a1, c2, c3);
        featp[jg4 + 0][row] = c0; featp[jg4 + 1][row] = c1;
        featp[jg4 + 2][row] = c2; featp[jg4 + 3][row] = c3;
    }

    // ---- S6 L1: phase hidden -> phS[row][k] ----
    {
        ulonglong2 PB = ld128(phase_b1 + j4);
        ulonglong2 PW[5];
#pragma unroll
        for (int k = 0; k < 5; k++) PW[k] = ld128(phase_w1 + k * 128 + j4);
#pragma unroll
        for (int t = 0; t < 2; t++) {
            const int n = t ? nb : na;
            float4 po = ld4(phase_onehot + 4 * n);
            float x[5] = {po.x, po.y, po.z, po.w, ee[t]};
            u64 lo = PB.x, hi = PB.y;
#pragma unroll
            for (int k = 0; k < 5; k++) {
                u64 d = dup2(x[k]);
                lo = ffma2(d, PW[k].x, lo);
                hi = ffma2(d, PW[k].y, hi);
            }
            float2 r0 = relu2(lo), r1 = relu2(hi);
            st4(phS + (2 * warp + t) * 132 + j4, make_float4(r0.x, r0.y, r1.x, r1.y));
        }
    }
    __syncthreads();

    // ---- S6 L2 partial: quadrant coop ----
    {
        const int kh = warp & 1, rh = warp >> 1;
        const int k0 = 64 * kh, r0 = 4 * rh;
        float* Pp = kh ? Pp1 : Pp0;
        u64 acc[4][2];
#pragma unroll
        for (int r = 0; r < 4; r++) acc[r][0] = acc[r][1] = 0ULL;
        for (int k = k0; k < k0 + 64; k += 4) {
            float av[4][4];
#pragma unroll
            for (int r = 0; r < 4; r++) {
                float4 v = ld4(phS + (r0 + r) * 132 + k);
                av[r][0] = v.x; av[r][1] = v.y; av[r][2] = v.z; av[r][3] = v.w;
            }
#pragma unroll
            for (int kk = 0; kk < 4; kk++) {
                ulonglong2 w = ld128(phase_w2 + (k + kk) * 128 + j4);
#pragma unroll
                for (int r = 0; r < 4; r++) {
                    u64 d = dup2(av[r][kk]);
                    acc[r][0] = ffma2(d, w.x, acc[r][0]);
                    acc[r][1] = ffma2(d, w.y, acc[r][1]);
                }
            }
        }
#pragma unroll
        for (int r = 0; r < 4; r++) {
            float a0, a1, a2, a3; upk2(acc[r][0], a0, a1); upk2(acc[r][1], a2, a3);
            st4(Pp + (r0 + r) * 128 + j4, make_float4(a0, a1, a2, a3));
        }
    }
    __syncthreads();

    // ---- S6 final -> featp[64:192) ; S7 region ----
    {
        float4 b = ld4(phase_b2 + j4);
#pragma unroll
        for (int rr = 0; rr < 2; rr++) {
            const int r = 2 * warp + rr;
            float4 p0 = ld4(Pp0 + r * 128 + j4);
            float4 p1 = ld4(Pp1 + r * 128 + j4);
            featp[64 + j4 + 0][r] = relu(p0.x + p1.x + b.x);
            featp[64 + j4 + 1][r] = relu(p0.y + p1.y + b.y);
            featp[64 + j4 + 2][r] = relu(p0.z + p1.z + b.z);
            featp[64 + j4 + 3][r] = relu(p0.w + p1.w + b.w);
        }
    }
    if (lane < 16) {
        const int t = lane >> 3, f = lane & 7;
        const int n = t ? nb : na;
        int rid = region_ids[n];
        rid = min(max(rid, 0), 3);
        featp[192 + f][warp * 2 + t] = region_table[rid * 8 + f];
    }
    __syncthreads();

    // ---- S8 partial: warp = (k-half, j-half); thread owns 2 j; rows packed f32x2 ----
    {
        const int kh = warp & 1, jh = warp >> 1;
        const int j2 = jh * 64 + lane * 2;
        const int k0 = kh * 100;
        u64 acc[8];
#pragma unroll
        for (int r = 0; r < 8; r++) acc[r] = 0ULL;
#pragma unroll 4
        for (int k = k0; k < k0 + 100; k++) {
            u64 wk = ld64(head_w1 + k * 128 + j2);
            ulonglong2 fa = ld128(&featp[k][0]);   // rows 0-1, 2-3 packed
            ulonglong2 fb = ld128(&featp[k][4]);   // rows 4-5, 6-7 packed
            float f0, f1, f2, f3, f4, f5, f6, f7;
            upk2(fa.x, f0, f1); upk2(fa.y, f2, f3);
            upk2(fb.x, f4, f5); upk2(fb.y, f6, f7);
            acc[0] = ffma2(dup2(f0), wk, acc[0]); acc[1] = ffma2(dup2(f1), wk, acc[1]);
            acc[2] = ffma2(dup2(f2), wk, acc[2]); acc[3] = ffma2(dup2(f3), wk, acc[3]);
            acc[4] = ffma2(dup2(f4), wk, acc[4]); acc[5] = ffma2(dup2(f5), wk, acc[5]);
            acc[6] = ffma2(dup2(f6), wk, acc[6]); acc[7] = ffma2(dup2(f7), wk, acc[7]);
        }
        float* Pp8 = kh ? Pp8b : Pp8a;
#pragma unroll
        for (int r = 0; r < 8; r++)
            *reinterpret_cast<u64*>(Pp8 + r * 128 + j2) = acc[r];
    }
    __syncthreads();

    // ---- S8 final: warp combines its 2 rows, writes outputs ----
    {
        float4 b  = ld4(head_b1 + j4);
        float4 w2 = ld4(head_w2 + j4);
        float sums[2];
#pragma unroll
        for (int tt = 0; tt < 2; tt++) {
            const int r = 2 * warp + tt;
            float4 p0 = ld4(Pp8a + r * 128 + j4);
            float4 p1 = ld4(Pp8b + r * 128 + j4);
            float a0 = relu(p0.x + p1.x + b.x);
            float a1 = relu(p0.y + p1.y + b.y);
            float a2 = relu(p0.z + p1.z + b.z);
            float a3 = relu(p0.w + p1.w + b.w);
            float s = a0 * w2.x + a1 * w2.y + a2 * w2.z + a3 * w2.w;
#pragma unroll
            for (int off = 16; off > 0; off >>= 1)
                s += __shfl_xor_sync(0xffffffffu, s, off);
            sums[tt] = s;
        }
        if (lane == 0) {
            float ls = log_std[0];
            float sd = expf(ls);
            float bb2 = head_b2[0];
#pragma unroll
            for (int tt = 0; tt < 2; tt++) {
                const int n = n0 + tt;
                if (n < N) {
                    float mean = sums[tt] + bb2;
                    float nz = noise[n];
                    float act = mean + sd * nz;
                    out[n] = fminf(fmaxf(act, -1.0f), 1.0f);
                    out[N + n] = -0.5f * (nz * nz + 2.0f * ls + 1.8378770664093454f);
                }
            }
        }
    }
}

extern "C" void kernel_launch(void* const* d_in, const int* in_sizes, int n_in,
                              void* d_out, int out_size)
{
    const float* queue        = (const float*)d_in[0];
    const float* waiting      = (const float*)d_in[1];
    const float* phase_onehot = (const float*)d_in[2];
    const float* elapsed      = (const float*)d_in[3];
    const int*   region_ids   = (const int*)  d_in[4];
    const float* noise        = (const float*)d_in[5];
    const float* lane_w1      = (const float*)d_in[6];
    const float* lane_b1      = (const float*)d_in[7];
    const float* lane_w2      = (const float*)d_in[8];
    const float* lane_b2      = (const float*)d_in[9];
    const float* attn_in_w    = (const float*)d_in[10];
    const float* attn_in_b    = (const float*)d_in[11];
    const float* attn_out_w   = (const float*)d_in[12];
    const float* attn_out_b   = (const float*)d_in[13];
    const float* phase_w1     = (const float*)d_in[14];
    const float* phase_b1     = (const float*)d_in[15];
    const float* phase_w2     = (const float*)d_in[16];
    const float* phase_b2     = (const float*)d_in[17];
    const float* region_table = (const float*)d_in[18];
    const float* head_w1      = (const float*)d_in[19];
    const float* head_b1      = (const float*)d_in[20];
    const float* head_w2      = (const float*)d_in[21];
    const float* head_b2      = (const float*)d_in[22];
    const float* log_std      = (const float*)d_in[23];

    const int N = in_sizes[3];
    float* out = (float*)d_out;

    int blocks = (N + TLB - 1) / TLB;
    policy_kernel<<<blocks, NWARP * 32>>>(
        queue, waiting, phase_onehot, elapsed, region_ids, noise,
        lane_w1, lane_b1, lane_w2, lane_b2,
        attn_in_w, attn_in_b, attn_out_w, attn_out_b,
        phase_w1, phase_b1, phase_w2, phase_b2,
        region_table, head_w1, head_b1, head_w2, head_b2, log_std,
        out, N);
}

// round 12
// speedup vs baseline: 1.5968x; 1.0272x over previous
#include <cuda_runtime.h>
#include <math.h>

typedef unsigned long long u64;
typedef unsigned int u32;

#define NWARP 4
#define TLB   8
#define BUF   2208

__device__ __forceinline__ u64 pk2(float a, float b) {
    u64 r; asm("mov.b64 %0, {%1, %2};" : "=l"(r) : "r"(__float_as_uint(a)), "r"(__float_as_uint(b)));
    return r;
}
__device__ __forceinline__ void upk2(u64 v, float& a, float& b) {
    u32 x, y; asm("mov.b64 {%0, %1}, %2;" : "=r"(x), "=r"(y) : "l"(v));
    a = __uint_as_float(x); b = __uint_as_float(y);
}
__device__ __forceinline__ u64 dup2(float a) { return pk2(a, a); }
__device__ __forceinline__ u64 ffma2(u64 a, u64 b, u64 c) {
    u64 d; asm("fma.rn.f32x2 %0, %1, %2, %3;" : "=l"(d) : "l"(a), "l"(b), "l"(c)); return d;
}
__device__ __forceinline__ float2 relu2(u64 v) {
    float a, b; upk2(v, a, b); return make_float2(fmaxf(a, 0.f), fmaxf(b, 0.f));
}
__device__ __forceinline__ ulonglong2 ld128(const float* p) { return *reinterpret_cast<const ulonglong2*>(p); }
__device__ __forceinline__ u64 ld64(const float* p)         { return *reinterpret_cast<const u64*>(p); }
__device__ __forceinline__ float4 ld4(const float* p)       { return *reinterpret_cast<const float4*>(p); }
__device__ __forceinline__ void st4(float* p, float4 v)     { *reinterpret_cast<float4*>(p) = v; }
__device__ __forceinline__ float relu(float x) { return fmaxf(x, 0.f); }

__global__ __launch_bounds__(NWARP * 32)
void policy_kernel(
    const float* __restrict__ queue, const float* __restrict__ waiting,
    const float* __restrict__ phase_onehot, const float* __restrict__ elapsed,
    const int*   __restrict__ region_ids, const float* __restrict__ noise,
    const float* __restrict__ lane_w1, const float* __restrict__ lane_b1,
    const float* __restrict__ lane_w2, const float* __restrict__ lane_b2,
    const float* __restrict__ attn_in_w, const float* __restrict__ attn_in_b,
    const float* __restrict__ attn_out_w, const float* __restrict__ attn_out_b,
    const float* __restrict__ phase_w1, const float* __restrict__ phase_b1,
    const float* __restrict__ phase_w2, const float* __restrict__ phase_b2,
    const float* __restrict__ region_table,
    const float* __restrict__ head_w1, const float* __restrict__ head_b1,
    const float* __restrict__ head_w2, const float* __restrict__ head_b2,
    const float* __restrict__ log_std,
    float* __restrict__ out, int N)
{
    __shared__ float wb[NWARP][BUF];
    __shared__ float featp[200][12];

    const int tid  = threadIdx.x;
    const int warp = tid >> 5, lane = tid & 31;
    const int n0   = blockIdx.x * TLB + warp * 2;
    float* A     = wb[warp];
    float* Pp6   = &wb[0][0];          // [2][8][128] S6L2 partials (phase B)
    float* Pp8a  = &wb[1][0];          // S8 partials kh=0 (phase D)
    float* Pp5   = &wb[2][0];          // [2][4][128] S5b partials (phase A-B)
    float* Pp8b  = &wb[2][0];          // S8 partials kh=1 (phase D; Pp5 dead)
    float* phT   = &wb[3][0];          // [128][12] transposed phase hidden
    float* obarT = &featp[64][0];      // [64][12]; overwritten by S6-final (phase C)

    const int rgt = lane >> 4;
    const int jg4 = (lane & 15) * 4;
    const int j4  = lane * 4;

    const int na = min(n0,     N - 1);
    const int nb = min(n0 + 1, N - 1);
    const float ee[2] = { elapsed[na], elapsed[nb] };

    // ---- S1: lane MLP L1 -> h ----
    {
        ulonglong2 W0 = ld128(lane_w1 + j4);
        ulonglong2 W1 = ld128(lane_w1 + 128 + j4);
        ulonglong2 W2 = ld128(lane_w1 + 256 + j4);
        ulonglong2 BB = ld128(lane_b1 + j4);
#pragma unroll
        for (int t = 0; t < 2; t++) {
            const int n = t ? nb : na;
            float4 qv = ld4(queue + 4 * n);
            float4 wv = ld4(waiting + 4 * n);
            u64 ed = dup2(ee[t]);
            float qa[4] = {qv.x, qv.y, qv.z, qv.w};
            float wa[4] = {wv.x, wv.y, wv.z, wv.w};
#pragma unroll
            for (int l = 0; l < 4; l++) {
                u64 qd = dup2(qa[l]), wd = dup2(wa[l]);
                u64 lo = ffma2(qd, W0.x, BB.x); lo = ffma2(wd, W1.x, lo); lo = ffma2(ed, W2.x, lo);
                u64 hi = ffma2(qd, W0.y, BB.y); hi = ffma2(wd, W1.y, hi); hi = ffma2(ed, W2.y, hi);
                float2 r0 = relu2(lo), r1 = relu2(hi);
                st4(A + t * 528 + l * 128 + j4, make_float4(r0.x, r0.y, r1.x, r1.y));
            }
        }
    }
    __syncwarp();

    // ---- S2: lane MLP L2 -> emb ----
    {
        ulonglong2 bb = ld128(lane_b2 + jg4);
        u64 acc[4][2];
#pragma unroll
        for (int l = 0; l < 4; l++) { acc[l][0] = bb.x; acc[l][1] = bb.y; }
#pragma unroll 2
        for (int k = 0; k < 128; k += 4) {
            float hv[4][4];
#pragma unroll
            for (int l = 0; l < 4; l++) {
                float4 v = ld4(A + rgt * 528 + l * 128 + k);
                hv[l][0] = v.x; hv[l][1] = v.y; hv[l][2] = v.z; hv[l][3] = v.w;
            }
#pragma unroll
            for (int kk = 0; kk < 4; kk++) {
                ulonglong2 w = ld128(lane_w2 + (k + kk) * 64 + jg4);
#pragma unroll
                for (int l = 0; l < 4; l++) {
                    u64 d = dup2(hv[l][kk]);
                    acc[l][0] = ffma2(d, w.x, acc[l][0]);
                    acc[l][1] = ffma2(d, w.y, acc[l][1]);
                }
            }
        }
#pragma unroll
        for (int l = 0; l < 4; l++) {
            float2 r0 = relu2(acc[l][0]), r1 = relu2(acc[l][1]);
            st4(A + 1664 + rgt * 272 + l * 64 + jg4, make_float4(r0.x, r0.y, r1.x, r1.y));
        }
    }
    __syncwarp();

    // ---- S3: QKV ----
#pragma unroll
    for (int m = 0; m < 3; m++) {
        ulonglong2 bm = ld128(attn_in_b + 64 * m + jg4);
        u64 acc[4][2];
#pragma unroll
        for (int l = 0; l < 4; l++) { acc[l][0] = bm.x; acc[l][1] = bm.y; }
#pragma unroll 2
        for (int k = 0; k < 64; k += 4) {
            float ev[4][4];
#pragma unroll
            for (int l = 0; l < 4; l++) {
                float4 v = ld4(A + 1664 + rgt * 272 + l * 64 + k);
                ev[l][0] = v.x; ev[l][1] = v.y; ev[l][2] = v.z; ev[l][3] = v.w;
            }
#pragma unroll
            for (int kk = 0; kk < 4; kk++) {
                ulonglong2 w = ld128(attn_in_w + (k + kk) * 192 + 64 * m + jg4);
#pragma unroll
                for (int l = 0; l < 4; l++) {
                    u64 d = dup2(ev[l][kk]);
                    acc[l][0] = ffma2(d, w.x, acc[l][0]);
                    acc[l][1] = ffma2(d, w.y, acc[l][1]);
                }
            }
        }
#pragma unroll
        for (int l = 0; l < 4; l++) {
            float a0, a1, a2, a3; upk2(acc[l][0], a0, a1); upk2(acc[l][1], a2, a3);
            st4(A + rgt * 816 + l * 200 + m * 64 + jg4, make_float4(a0, a1, a2, a3));
        }
    }
    __syncwarp();

    // ---- S4: attention ----
    {
        const int t4 = rgt, r4 = lane & 15, hh = r4 >> 2, ql = r4 & 3;
        const float* qb = A + t4 * 816 + ql * 200 + hh * 16;
        float q[16];
#pragma unroll
        for (int i = 0; i < 4; i++) {
            float4 v = ld4(qb + 4 * i);
            q[4*i] = v.x; q[4*i+1] = v.y; q[4*i+2] = v.z; q[4*i+3] = v.w;
        }
        float sc[4];
#pragma unroll
        for (int kl = 0; kl < 4; kl++) {
            const float* kb = A + t4 * 816 + kl * 200 + 64 + hh * 16;
            float d = 0.f;
#pragma unroll
            for (int i = 0; i < 4; i++) {
                float4 v = ld4(kb + 4 * i);
                d = fmaf(q[4*i], v.x, d); d = fmaf(q[4*i+1], v.y, d);
                d = fmaf(q[4*i+2], v.z, d); d = fmaf(q[4*i+3], v.w, d);
            }
            sc[kl] = d * 0.25f;
        }
        float mx = fmaxf(fmaxf(sc[0], sc[1]), fmaxf(sc[2], sc[3]));
        float es = 0.f;
#pragma unroll
        for (int kl = 0; kl < 4; kl++) { sc[kl] = __expf(sc[kl] - mx); es += sc[kl]; }
        float inv = 1.f / es;
#pragma unroll
        for (int kl = 0; kl < 4; kl++) sc[kl] *= inv;
        float o[16];
#pragma unroll
        for (int i = 0; i < 4; i++) {
            float ox = 0.f, oy = 0.f, oz = 0.f, ow = 0.f;
#pragma unroll
            for (int kl = 0; kl < 4; kl++) {
                float4 v = ld4(A + t4 * 816 + kl * 200 + 128 + hh * 16 + 4 * i);
                ox = fmaf(sc[kl], v.x, ox); oy = fmaf(sc[kl], v.y, oy);
                oz = fmaf(sc[kl], v.z, oz); ow = fmaf(sc[kl], v.w, ow);
            }
            o[4*i] = ox; o[4*i+1] = oy; o[4*i+2] = oz; o[4*i+3] = ow;
        }
        __syncwarp();
#pragma unroll
        for (int i = 0; i < 4; i++)
            st4(A + t4 * 280 + ql * 68 + hh * 16 + 4 * i,
                make_float4(o[4*i], o[4*i+1], o[4*i+2], o[4*i+3]));
    }
    __syncwarp();

    // ---- S5a: obar -> obarT[k][row] (transposed into featp rows 64..128) ----
#pragma unroll
    for (int ii = 0; ii < 4; ii++) {
        int i = lane + 32 * ii;
        int t = i >> 6, jj = i & 63;
        float s = A[t*280 + jj] + A[t*280 + 68 + jj] + A[t*280 + 136 + jj] + A[t*280 + 204 + jj];
        obarT[jj * 12 + 2 * warp + t] = 0.25f * s;
    }
    __syncthreads();   // per-warp A dead; obarT complete

    // ==== Phase A: S5b partial (k-split) + S6L1 (transposed) ====
    {
        const int kh = warp & 1, jh = warp >> 1;
        const int j = jh * 32 + lane;
        const int k0 = kh * 32;
        u64 acc[4] = {0ULL, 0ULL, 0ULL, 0ULL};
#pragma unroll 8
        for (int k = k0; k < k0 + 32; k++) {
            u64 wd = dup2(attn_out_w[k * 64 + j]);
            ulonglong2 fa = ld128(obarT + k * 12);       // rows 0-1, 2-3 packed
            ulonglong2 fb = ld128(obarT + k * 12 + 4);   // rows 4-5, 6-7 packed
            acc[0] = ffma2(fa.x, wd, acc[0]); acc[1] = ffma2(fa.y, wd, acc[1]);
            acc[2] = ffma2(fb.x, wd, acc[2]); acc[3] = ffma2(fb.y, wd, acc[3]);
        }
#pragma unroll
        for (int rp = 0; rp < 4; rp++)
            *reinterpret_cast<u64*>(Pp5 + kh * 512 + rp * 128 + j * 2) = acc[rp];
    }
    {
        float4 poa = ld4(phase_onehot + 4 * na);
        float4 pob = ld4(phase_onehot + 4 * nb);
        float xa[5] = {poa.x, poa.y, poa.z, poa.w, ee[0]};
        float xb[5] = {pob.x, pob.y, pob.z, pob.w, ee[1]};
#pragma unroll
        for (int i = 0; i < 4; i++) {
            int h1 = lane + 32 * i;
            float b  = phase_b1[h1];
            float w0 = phase_w1[h1],       w1 = phase_w1[128 + h1], w2 = phase_w1[256 + h1];
            float w3 = phase_w1[384 + h1], w4 = phase_w1[512 + h1];
            float va = b + xa[0]*w0 + xa[1]*w1 + xa[2]*w2 + xa[3]*w3 + xa[4]*w4;
            float vb = b + xb[0]*w0 + xb[1]*w1 + xb[2]*w2 + xb[3]*w3 + xb[4]*w4;
            phT[h1 * 12 + 2 * warp + 0] = relu(va);
            phT[h1 * 12 + 2 * warp + 1] = relu(vb);
        }
    }
    __syncthreads();

    // ==== Phase B: S5b final -> featp[0:64) ; S6L2 partial (S8-style) ====
    {
#pragma unroll
        for (int jj2 = 0; jj2 < 2; jj2++) {
            const int jj = lane + 32 * jj2;
            u64 p0 = *reinterpret_cast<const u64*>(Pp5 + warp * 128 + jj * 2);
            u64 p1 = *reinterpret_cast<const u64*>(Pp5 + 512 + warp * 128 + jj * 2);
            float a0, a1, b0, b1; upk2(p0, a0, a1); upk2(p1, b0, b1);
            float bias = attn_out_b[jj];
            featp[jj][2 * warp + 0] = a0 + b0 + bias;
            featp[jj][2 * warp + 1] = a1 + b1 + bias;
        }
    }
    {
        const int kh = warp & 1, jh = warp >> 1;
        const int j2 = jh * 64 + lane * 2;
        const int k0 = kh * 64;
        u64 acc[8];
#pragma unroll
        for (int r = 0; r < 8; r++) acc[r] = 0ULL;
#pragma unroll 4
        for (int k = k0; k < k0 + 64; k++) {
            u64 wk = ld64(phase_w2 + k * 128 + j2);
            float4 fa = ld4(phT + k * 12);
            float4 fb = ld4(phT + k * 12 + 4);
            acc[0] = ffma2(dup2(fa.x), wk, acc[0]); acc[1] = ffma2(dup2(fa.y), wk, acc[1]);
            acc[2] = ffma2(dup2(fa.z), wk, acc[2]); acc[3] = ffma2(dup2(fa.w), wk, acc[3]);
            acc[4] = ffma2(dup2(fb.x), wk, acc[4]); acc[5] = ffma2(dup2(fb.y), wk, acc[5]);
            acc[6] = ffma2(dup2(fb.z), wk, acc[6]); acc[7] = ffma2(dup2(fb.w), wk, acc[7]);
        }
#pragma unroll
        for (int r = 0; r < 8; r++)
            *reinterpret_cast<u64*>(Pp6 + kh * 1024 + r * 128 + j2) = acc[r];
    }
    __syncthreads();

    // ==== Phase C: S6 final -> featp[64:192) ; S7 region -> featp[192:200) ====
    {
        float4 b2 = ld4(phase_b2 + j4);
#pragma unroll
        for (int tt = 0; tt < 2; tt++) {
            const int r = 2 * warp + tt;
            float4 p0 = ld4(Pp6 + r * 128 + j4);
            float4 p1 = ld4(Pp6 + 1024 + r * 128 + j4);
            featp[64 + j4 + 0][r] = relu(p0.x + p1.x + b2.x);
            featp[64 + j4 + 1][r] = relu(p0.y + p1.y + b2.y);
            featp[64 + j4 + 2][r] = relu(p0.z + p1.z + b2.z);
            featp[64 + j4 + 3][r] = relu(p0.w + p1.w + b2.w);
        }
    }
    if (lane < 16) {
        const int t = lane >> 3, f = lane & 7;
        const int n = t ? nb : na;
        int rid = region_ids[n];
        rid = min(max(rid, 0), 3);
        featp[192 + f][warp * 2 + t] = region_table[rid * 8 + f];
    }
    __syncthreads();

    // ==== Phase D: S8 partial (k-half x j-half) ====
    {
        const int kh = warp & 1, jh = warp >> 1;
        const int j2 = jh * 64 + lane * 2;
        const int k0 = kh * 100;
        u64 acc[8];
#pragma unroll
        for (int r = 0; r < 8; r++) acc[r] = 0ULL;
#pragma unroll 4
        for (int k = k0; k < k0 + 100; k++) {
            u64 wk = ld64(head_w1 + k * 128 + j2);
            ulonglong2 fa = ld128(&featp[k][0]);
            ulonglong2 fb = ld128(&featp[k][4]);
            float f0, f1, f2, f3, f4, f5, f6, f7;
            upk2(fa.x, f0, f1); upk2(fa.y, f2, f3);
            upk2(fb.x, f4, f5); upk2(fb.y, f6, f7);
            acc[0] = ffma2(dup2(f0), wk, acc[0]); acc[1] = ffma2(dup2(f1), wk, acc[1]);
            acc[2] = ffma2(dup2(f2), wk, acc[2]); acc[3] = ffma2(dup2(f3), wk, acc[3]);
            acc[4] = ffma2(dup2(f4), wk, acc[4]); acc[5] = ffma2(dup2(f5), wk, acc[5]);
            acc[6] = ffma2(dup2(f6), wk, acc[6]); acc[7] = ffma2(dup2(f7), wk, acc[7]);
        }
        float* Pp8 = kh ? Pp8b : Pp8a;
#pragma unroll
        for (int r = 0; r < 8; r++)
            *reinterpret_cast<u64*>(Pp8 + r * 128 + j2) = acc[r];
    }
    __syncthreads();

    // ==== Phase E: S8 final ====
    {
        float4 b  = ld4(head_b1 + j4);
        float4 w2 = ld4(head_w2 + j4);
        float sums[2];
#pragma unroll
        for (int tt = 0; tt < 2; tt++) {
            const int r = 2 * warp + tt;
            float4 p0 = ld4(Pp8a + r * 128 + j4);
            float4 p1 = ld4(Pp8b + r * 128 + j4);
            float a0 = relu(p0.x + p1.x + b.x);
            float a1 = relu(p0.y + p1.y + b.y);
            float a2 = relu(p0.z + p1.z + b.z);
            float a3 = relu(p0.w + p1.w + b.w);
            float s = a0 * w2.x + a1 * w2.y + a2 * w2.z + a3 * w2.w;
#pragma unroll
            for (int off = 16; off > 0; off >>= 1)
                s += __shfl_xor_sync(0xffffffffu, s, off);
            sums[tt] = s;
        }
        if (lane == 0) {
            float ls = log_std[0];
            float sd = expf(ls);
            float bb2 = head_b2[0];
#pragma unroll
            for (int tt = 0; tt < 2; tt++) {
                const int n = n0 + tt;
                if (n < N) {
                    float mean = sums[tt] + bb2;
                    float nz = noise[n];
                    float act = mean + sd * nz;
                    out[n] = fminf(fmaxf(act, -1.0f), 1.0f);
                    out[N + n] = -0.5f * (nz * nz + 2.0f * ls + 1.8378770664093454f);
                }
            }
        }
    }
}

extern "C" void kernel_launch(void* const* d_in, const int* in_sizes, int n_in,
                              void* d_out, int out_size)
{
    const float* queue        = (const float*)d_in[0];
    const float* waiting      = (const float*)d_in[1];
    const float* phase_onehot = (const float*)d_in[2];
    const float* elapsed      = (const float*)d_in[3];
    const int*   region_ids   = (const int*)  d_in[4];
    const float* noise        = (const float*)d_in[5];
    const float* lane_w1      = (const float*)d_in[6];
    const float* lane_b1      = (const float*)d_in[7];
    const float* lane_w2      = (const float*)d_in[8];
    const float* lane_b2      = (const float*)d_in[9];
    const float* attn_in_w    = (const float*)d_in[10];
    const float* attn_in_b    = (const float*)d_in[11];
    const float* attn_out_w   = (const float*)d_in[12];
    const float* attn_out_b   = (const float*)d_in[13];
    const float* phase_w1     = (const float*)d_in[14];
    const float* phase_b1     = (const float*)d_in[15];
    const float* phase_w2     = (const float*)d_in[16];
    const float* phase_b2     = (const float*)d_in[17];
    const float* region_table = (const float*)d_in[18];
    const float* head_w1      = (const float*)d_in[19];
    const float* head_b1      = (const float*)d_in[20];
    const float* head_w2      = (const float*)d_in[21];
    const float* head_b2      = (const float*)d_in[22];
    const float* log_std      = (const float*)d_in[23];

    const int N = in_sizes[3];
    float* out = (float*)d_out;

    int blocks = (N + TLB - 1) / TLB;
    policy_kernel<<<blocks, NWARP * 32>>>(
        queue, waiting, phase_onehot, elapsed, region_ids, noise,
        lane_w1, lane_b1, lane_w2, lane_b2,
        attn_in_w, attn_in_b, attn_out_w, attn_out_b,
        phase_w1, phase_b1, phase_w2, phase_b2,
        region_table, head_w1, head_b1, head_w2, head_b2, log_std,
        out, N);
}

// round 15
// speedup vs baseline: 1.6192x; 1.0140x over previous
#include <cuda_runtime.h>
#include <math.h>

typedef unsigned long long u64;
typedef unsigned int u32;

#define NWARP 4
#define TLB   8
#define BUF   2208

__device__ __forceinline__ u64 pk2(float a, float b) {
    u64 r; asm("mov.b64 %0, {%1, %2};" : "=l"(r) : "r"(__float_as_uint(a)), "r"(__float_as_uint(b)));
    return r;
}
__device__ __forceinline__ void upk2(u64 v, float& a, float& b) {
    u32 x, y; asm("mov.b64 {%0, %1}, %2;" : "=r"(x), "=r"(y) : "l"(v));
    a = __uint_as_float(x); b = __uint_as_float(y);
}
__device__ __forceinline__ u64 dup2(float a) { return pk2(a, a); }
__device__ __forceinline__ u64 ffma2(u64 a, u64 b, u64 c) {
    u64 d; asm("fma.rn.f32x2 %0, %1, %2, %3;" : "=l"(d) : "l"(a), "l"(b), "l"(c)); return d;
}
__device__ __forceinline__ float2 relu2(u64 v) {
    float a, b; upk2(v, a, b); return make_float2(fmaxf(a, 0.f), fmaxf(b, 0.f));
}
__device__ __forceinline__ ulonglong2 ld128(const float* p) { return *reinterpret_cast<const ulonglong2*>(p); }
__device__ __forceinline__ u64 ld64(const float* p)         { return *reinterpret_cast<const u64*>(p); }
__device__ __forceinline__ float4 ld4(const float* p)       { return *reinterpret_cast<const float4*>(p); }
__device__ __forceinline__ void st4(float* p, float4 v)     { *reinterpret_cast<float4*>(p) = v; }
__device__ __forceinline__ float relu(float x) { return fmaxf(x, 0.f); }

__global__ __launch_bounds__(NWARP * 32)
void policy_kernel(
    const float* __restrict__ queue, const float* __restrict__ waiting,
    const float* __restrict__ phase_onehot, const float* __restrict__ elapsed,
    const int*   __restrict__ region_ids, const float* __restrict__ noise,
    const float* __restrict__ lane_w1, const float* __restrict__ lane_b1,
    const float* __restrict__ lane_w2, const float* __restrict__ lane_b2,
    const float* __restrict__ attn_in_w, const float* __restrict__ attn_in_b,
    const float* __restrict__ attn_out_w, const float* __restrict__ attn_out_b,
    const float* __restrict__ phase_w1, const float* __restrict__ phase_b1,
    const float* __restrict__ phase_w2, const float* __restrict__ phase_b2,
    const float* __restrict__ region_table,
    const float* __restrict__ head_w1, const float* __restrict__ head_b1,
    const float* __restrict__ head_w2, const float* __restrict__ head_b2,
    const float* __restrict__ log_std,
    float* __restrict__ out, int N)
{
    __shared__ float wb[NWARP][BUF];
    __shared__ float featp[200][12];

    const int tid  = threadIdx.x;
    const int warp = tid >> 5, lane = tid & 31;
    const int n0   = blockIdx.x * TLB + warp * 2;
    float* A     = wb[warp];
    float* Pp6   = &wb[0][0];          // [2][8][128] S6L2 partials
    float* Pp8a  = &wb[1][0];          // S8 partials kh=0
    float* Pp5   = &wb[2][0];          // [2][4][128] S5b partials
    float* Pp8b  = &wb[2][0];          // S8 partials kh=1 (Pp5 dead)
    float* phT   = &wb[3][0];          // [128][12] transposed phase hidden
    float* obarT = &featp[64][0];      // [64][12]; overwritten by S6-final

    const int rgt = lane >> 4;
    const int jg4 = (lane & 15) * 4;
    const int j4  = lane * 4;

    const int na = min(n0,     N - 1);
    const int nb = min(n0 + 1, N - 1);
    const float ee[2] = { elapsed[na], elapsed[nb] };

    // ---- S1: lane MLP L1 -> h[t][l][128] (t*528 + l*128) ----
    {
        ulonglong2 W0 = ld128(lane_w1 + j4);
        ulonglong2 W1 = ld128(lane_w1 + 128 + j4);
        ulonglong2 W2 = ld128(lane_w1 + 256 + j4);
        ulonglong2 BB = ld128(lane_b1 + j4);
#pragma unroll
        for (int t = 0; t < 2; t++) {
            const int n = t ? nb : na;
            float4 qv = ld4(queue + 4 * n);
            float4 wv = ld4(waiting + 4 * n);
            u64 ed = dup2(ee[t]);
            float qa[4] = {qv.x, qv.y, qv.z, qv.w};
            float wa[4] = {wv.x, wv.y, wv.z, wv.w};
#pragma unroll
            for (int l = 0; l < 4; l++) {
                u64 qd = dup2(qa[l]), wd = dup2(wa[l]);
                u64 lo = ffma2(qd, W0.x, BB.x); lo = ffma2(wd, W1.x, lo); lo = ffma2(ed, W2.x, lo);
                u64 hi = ffma2(qd, W0.y, BB.y); hi = ffma2(wd, W1.y, hi); hi = ffma2(ed, W2.y, hi);
                float2 r0 = relu2(lo), r1 = relu2(hi);
                st4(A + t * 528 + l * 128 + j4, make_float4(r0.x, r0.y, r1.x, r1.y));
            }
        }
    }
    __syncwarp();

    // ---- S2: lane MLP L2 -> emb[1664 + rgt*272 + l*64] ----
    {
        ulonglong2 bb = ld128(lane_b2 + jg4);
        u64 acc[4][2];
#pragma unroll
        for (int l = 0; l < 4; l++) { acc[l][0] = bb.x; acc[l][1] = bb.y; }
#pragma unroll 2
        for (int k = 0; k < 128; k += 4) {
            float hv[4][4];
#pragma unroll
            for (int l = 0; l < 4; l++) {
                float4 v = ld4(A + rgt * 528 + l * 128 + k);
                hv[l][0] = v.x; hv[l][1] = v.y; hv[l][2] = v.z; hv[l][3] = v.w;
            }
#pragma unroll
            for (int kk = 0; kk < 4; kk++) {
                ulonglong2 w = ld128(lane_w2 + (k + kk) * 64 + jg4);
#pragma unroll
                for (int l = 0; l < 4; l++) {
                    u64 d = dup2(hv[l][kk]);
                    acc[l][0] = ffma2(d, w.x, acc[l][0]);
                    acc[l][1] = ffma2(d, w.y, acc[l][1]);
                }
            }
        }
#pragma unroll
        for (int l = 0; l < 4; l++) {
            float2 r0 = relu2(acc[l][0]), r1 = relu2(acc[l][1]);
            st4(A + 1664 + rgt * 272 + l * 64 + jg4, make_float4(r0.x, r0.y, r1.x, r1.y));
        }
    }
    __syncwarp();

    // ---- S3: QKV -> qkv[t*784 + l*196 + m*64 + j] (conflict-free strides) ----
#pragma unroll
    for (int m = 0; m < 3; m++) {
        ulonglong2 bm = ld128(attn_in_b + 64 * m + jg4);
        u64 acc[4][2];
#pragma unroll
        for (int l = 0; l < 4; l++) { acc[l][0] = bm.x; acc[l][1] = bm.y; }
#pragma unroll 2
        for (int k = 0; k < 64; k += 4) {
            float ev[4][4];
#pragma unroll
            for (int l = 0; l < 4; l++) {
                float4 v = ld4(A + 1664 + rgt * 272 + l * 64 + k);
                ev[l][0] = v.x; ev[l][1] = v.y; ev[l][2] = v.z; ev[l][3] = v.w;
            }
#pragma unroll
            for (int kk = 0; kk < 4; kk++) {
                ulonglong2 w = ld128(attn_in_w + (k + kk) * 192 + 64 * m + jg4);
#pragma unroll
                for (int l = 0; l < 4; l++) {
                    u64 d = dup2(ev[l][kk]);
                    acc[l][0] = ffma2(d, w.x, acc[l][0]);
                    acc[l][1] = ffma2(d, w.y, acc[l][1]);
                }
            }
        }
#pragma unroll
        for (int l = 0; l < 4; l++) {
            float a0, a1, a2, a3; upk2(acc[l][0], a0, a1); upk2(acc[l][1], a2, a3);
            st4(A + rgt * 784 + l * 196 + m * 64 + jg4, make_float4(a0, a1, a2, a3));
        }
    }
    __syncwarp();

    // ---- S4 fused: attention probs -> c_k = mean_q attn -> obar slice -> obarT ----
    {
        const int t4 = rgt, r4 = lane & 15, hh = r4 >> 2, ql = r4 & 3;
        const float* base = A + t4 * 784;
        const float* qb = base + ql * 196 + hh * 16;
        float q[16];
#pragma unroll
        for (int i = 0; i < 4; i++) {
            float4 v = ld4(qb + 4 * i);
            q[4*i] = v.x; q[4*i+1] = v.y; q[4*i+2] = v.z; q[4*i+3] = v.w;
        }
        float sc[4];
#pragma unroll
        for (int kl = 0; kl < 4; kl++) {
            const float* kb = base + kl * 196 + 64 + hh * 16;
            float d = 0.f;
#pragma unroll
            for (int i = 0; i < 4; i++) {
                float4 v = ld4(kb + 4 * i);
                d = fmaf(q[4*i], v.x, d); d = fmaf(q[4*i+1], v.y, d);
                d = fmaf(q[4*i+2], v.z, d); d = fmaf(q[4*i+3], v.w, d);
            }
            sc[kl] = d * 0.25f;
        }
        float mx = fmaxf(fmaxf(sc[0], sc[1]), fmaxf(sc[2], sc[3]));
        float es = 0.f;
#pragma unroll
        for (int kl = 0; kl < 4; kl++) { sc[kl] = __expf(sc[kl] - mx); es += sc[kl]; }
        float inv = 1.f / es;
        // normalized probs; c_k = 0.25 * sum over the 4 q-lanes (bits 0-1 of lane)
        float c[4];
#pragma unroll
        for (int kl = 0; kl < 4; kl++) {
            float p = sc[kl] * inv;
            p += __shfl_xor_sync(0xffffffffu, p, 1);
            p += __shfl_xor_sync(0xffffffffu, p, 2);
            c[kl] = 0.25f * p;
        }
        // obar slice: e = hh*16 + ql*4 + (0..3);  obar[e] = sum_k c_k * v[k][e]
        float4 vb = make_float4(0.f, 0.f, 0.f, 0.f);
#pragma unroll
        for (int kl = 0; kl < 4; kl++) {
            float4 v = ld4(base + kl * 196 + 128 + hh * 16 + ql * 4);
            vb.x = fmaf(c[kl], v.x, vb.x); vb.y = fmaf(c[kl], v.y, vb.y);
            vb.z = fmaf(c[kl], v.z, vb.z); vb.w = fmaf(c[kl], v.w, vb.w);
        }
        const int e0 = hh * 16 + ql * 4, col = 2 * warp + t4;
        obarT[(e0 + 0) * 12 + col] = vb.x;
        obarT[(e0 + 1) * 12 + col] = vb.y;
        obarT[(e0 + 2) * 12 + col] = vb.z;
        obarT[(e0 + 3) * 12 + col] = vb.w;
    }
    __syncthreads();   // per-warp A dead; obarT complete

    // ==== Phase A: S5b partial (k-split) + S6L1 (transposed) ====
    {
        const int kh = warp & 1, jh = warp >> 1;
        const int j = jh * 32 + lane;
        const int k0 = kh * 32;
        u64 acc[4] = {0ULL, 0ULL, 0ULL, 0ULL};
#pragma unroll 8
        for (int k = k0; k < k0 + 32; k++) {
            u64 wd = dup2(attn_out_w[k * 64 + j]);
            ulonglong2 fa = ld128(obarT + k * 12);
            ulonglong2 fb = ld128(obarT + k * 12 + 4);
            acc[0] = ffma2(fa.x, wd, acc[0]); acc[1] = ffma2(fa.y, wd, acc[1]);
            acc[2] = ffma2(fb.x, wd, acc[2]); acc[3] = ffma2(fb.y, wd, acc[3]);
        }
#pragma unroll
        for (int rp = 0; rp < 4; rp++)
            *reinterpret_cast<u64*>(Pp5 + kh * 512 + rp * 128 + j * 2) = acc[rp];
    }
    {
        float4 poa = ld4(phase_onehot + 4 * na);
        float4 pob = ld4(phase_onehot + 4 * nb);
        float xa[5] = {poa.x, poa.y, poa.z, poa.w, ee[0]};
        float xb[5] = {pob.x, pob.y, pob.z, pob.w, ee[1]};
#pragma unroll
        for (int i = 0; i < 4; i++) {
            int h1 = lane + 32 * i;
            float b  = phase_b1[h1];
            float w0 = phase_w1[h1],       w1 = phase_w1[128 + h1], w2 = phase_w1[256 + h1];
            float w3 = phase_w1[384 + h1], w4 = phase_w1[512 + h1];
            float va = b + xa[0]*w0 + xa[1]*w1 + xa[2]*w2 + xa[3]*w3 + xa[4]*w4;
            float vb = b + xb[0]*w0 + xb[1]*w1 + xb[2]*w2 + xb[3]*w3 + xb[4]*w4;
            phT[h1 * 12 + 2 * warp + 0] = relu(va);
            phT[h1 * 12 + 2 * warp + 1] = relu(vb);
        }
    }
    __syncthreads();

    // ==== Phase B: S5b final -> featp[0:64) ; S6L2 partial ====
    {
#pragma unroll
        for (int jj2 = 0; jj2 < 2; jj2++) {
            const int jj = lane + 32 * jj2;
            u64 p0 = *reinterpret_cast<const u64*>(Pp5 + warp * 128 + jj * 2);
            u64 p1 = *reinterpret_cast<const u64*>(Pp5 + 512 + warp * 128 + jj * 2);
            float a0, a1, b0, b1; upk2(p0, a0, a1); upk2(p1, b0, b1);
            float bias = attn_out_b[jj];
            featp[jj][2 * warp + 0] = a0 + b0 + bias;
            featp[jj][2 * warp + 1] = a1 + b1 + bias;
        }
    }
    {
        const int kh = warp & 1, jh = warp >> 1;
        const int j2 = jh * 64 + lane * 2;
        const int k0 = kh * 64;
        u64 acc[8];
#pragma unroll
        for (int r = 0; r < 8; r++) acc[r] = 0ULL;
#pragma unroll 4
        for (int k = k0; k < k0 + 64; k++) {
            u64 wk = ld64(phase_w2 + k * 128 + j2);
            float4 fa = ld4(phT + k * 12);
            float4 fb = ld4(phT + k * 12 + 4);
            acc[0] = ffma2(dup2(fa.x), wk, acc[0]); acc[1] = ffma2(dup2(fa.y), wk, acc[1]);
            acc[2] = ffma2(dup2(fa.z), wk, acc[2]); acc[3] = ffma2(dup2(fa.w), wk, acc[3]);
            acc[4] = ffma2(dup2(fb.x), wk, acc[4]); acc[5] = ffma2(dup2(fb.y), wk, acc[5]);
            acc[6] = ffma2(dup2(fb.z), wk, acc[6]); acc[7] = ffma2(dup2(fb.w), wk, acc[7]);
        }
#pragma unroll
        for (int r = 0; r < 8; r++)
            *reinterpret_cast<u64*>(Pp6 + kh * 1024 + r * 128 + j2) = acc[r];
    }
    __syncthreads();

    // ==== Phase C: S6 final -> featp[64:192) ; S7 region ====
    {
        float4 b2 = ld4(phase_b2 + j4);
#pragma unroll
        for (int tt = 0; tt < 2; tt++) {
            const int r = 2 * warp + tt;
            float4 p0 = ld4(Pp6 + r * 128 + j4);
            float4 p1 = ld4(Pp6 + 1024 + r * 128 + j4);
            featp[64 + j4 + 0][r] = relu(p0.x + p1.x + b2.x);
            featp[64 + j4 + 1][r] = relu(p0.y + p1.y + b2.y);
            featp[64 + j4 + 2][r] = relu(p0.z + p1.z + b2.z);
            featp[64 + j4 + 3][r] = relu(p0.w + p1.w + b2.w);
        }
    }
    if (lane < 16) {
        const int t = lane >> 3, f = lane & 7;
        const int n = t ? nb : na;
        int rid = region_ids[n];
        rid = min(max(rid, 0), 3);
        featp[192 + f][warp * 2 + t] = region_table[rid * 8 + f];
    }
    __syncthreads();

    // ==== Phase D: S8 partial (k-half x j-half) ====
    {
        const int kh = warp & 1, jh = warp >> 1;
        const int j2 = jh * 64 + lane * 2;
        const int k0 = kh * 100;
        u64 acc[8];
#pragma unroll
        for (int r = 0; r < 8; r++) acc[r] = 0ULL;
#pragma unroll 4
        for (int k = k0; k < k0 + 100; k++) {
            u64 wk = ld64(head_w1 + k * 128 + j2);
            ulonglong2 fa = ld128(&featp[k][0]);
            ulonglong2 fb = ld128(&featp[k][4]);
            float f0, f1, f2, f3, f4, f5, f6, f7;
            upk2(fa.x, f0, f1); upk2(fa.y, f2, f3);
            upk2(fb.x, f4, f5); upk2(fb.y, f6, f7);
            acc[0] = ffma2(dup2(f0), wk, acc[0]); acc[1] = ffma2(dup2(f1), wk, acc[1]);
            acc[2] = ffma2(dup2(f2), wk, acc[2]); acc[3] = ffma2(dup2(f3), wk, acc[3]);
            acc[4] = ffma2(dup2(f4), wk, acc[4]); acc[5] = ffma2(dup2(f5), wk, acc[5]);
            acc[6] = ffma2(dup2(f6), wk, acc[6]); acc[7] = ffma2(dup2(f7), wk, acc[7]);
        }
        float* Pp8 = kh ? Pp8b : Pp8a;
#pragma unroll
        for (int r = 0; r < 8; r++)
            *reinterpret_cast<u64*>(Pp8 + r * 128 + j2) = acc[r];
    }
    __syncthreads();

    // ==== Phase E: S8 final ====
    {
        float4 b  = ld4(head_b1 + j4);
        float4 w2 = ld4(head_w2 + j4);
        float sums[2];
#pragma unroll
        for (int tt = 0; tt < 2; tt++) {
            const int r = 2 * warp + tt;
            float4 p0 = ld4(Pp8a + r * 128 + j4);
            float4 p1 = ld4(Pp8b + r * 128 + j4);
            float a0 = relu(p0.x + p1.x + b.x);
            float a1 = relu(p0.y + p1.y + b.y);
            float a2 = relu(p0.z + p1.z + b.z);
            float a3 = relu(p0.w + p1.w + b.w);
            float s = a0 * w2.x + a1 * w2.y + a2 * w2.z + a3 * w2.w;
#pragma unroll
            for (int off = 16; off > 0; off >>= 1)
                s += __shfl_xor_sync(0xffffffffu, s, off);
            sums[tt] = s;
        }
        if (lane == 0) {
            float ls = log_std[0];
            float sd = expf(ls);
            float bb2 = head_b2[0];
#pragma unroll
            for (int tt = 0; tt < 2; tt++) {
                const int n = n0 + tt;
                if (n < N) {
                    float mean = sums[tt] + bb2;
                    float nz = noise[n];
                    float act = mean + sd * nz;
                    out[n] = fminf(fmaxf(act, -1.0f), 1.0f);
                    out[N + n] = -0.5f * (nz * nz + 2.0f * ls + 1.8378770664093454f);
                }
            }
        }
    }
}

extern "C" void kernel_launch(void* const* d_in, const int* in_sizes, int n_in,
                              void* d_out, int out_size)
{
    const float* queue        = (const float*)d_in[0];
    const float* waiting      = (const float*)d_in[1];
    const float* phase_onehot = (const float*)d_in[2];
    const float* elapsed      = (const float*)d_in[3];
    const int*   region_ids   = (const int*)  d_in[4];
    const float* noise        = (const float*)d_in[5];
    const float* lane_w1      = (const float*)d_in[6];
    const float* lane_b1      = (const float*)d_in[7];
    const float* lane_w2      = (const float*)d_in[8];
    const float* lane_b2      = (const float*)d_in[9];
    const float* attn_in_w    = (const float*)d_in[10];
    const float* attn_in_b    = (const float*)d_in[11];
    const float* attn_out_w   = (const float*)d_in[12];
    const float* attn_out_b   = (const float*)d_in[13];
    const float* phase_w1     = (const float*)d_in[14];
    const float* phase_b1     = (const float*)d_in[15];
    const float* phase_w2     = (const float*)d_in[16];
    const float* phase_b2     = (const float*)d_in[17];
    const float* region_table = (const float*)d_in[18];
    const float* head_w1      = (const float*)d_in[19];
    const float* head_b1      = (const float*)d_in[20];
    const float* head_w2      = (const float*)d_in[21];
    const float* head_b2      = (const float*)d_in[22];
    const float* log_std      = (const float*)d_in[23];

    const int N = in_sizes[3];
    float* out = (float*)d_out;

    int blocks = (N + TLB - 1) / TLB;
    policy_kernel<<<blocks, NWARP * 32>>>(
        queue, waiting, phase_onehot, elapsed, region_ids, noise,
        lane_w1, lane_b1, lane_w2, lane_b2,
        attn_in_w, attn_in_b, attn_out_w, attn_out_b,
        phase_w1, phase_b1, phase_w2, phase_b2,
        region_table, head_w1, head_b1, head_w2, head_b2, log_std,
        out, N);
}

// round 16
// speedup vs baseline: 1.6600x; 1.0252x over previous
#include <cuda_runtime.h>
#include <math.h>

typedef unsigned long long u64;
typedef unsigned int u32;

#define NWARP 4
#define TLB   8
#define BUF   2208

__device__ __forceinline__ u64 pk2(float a, float b) {
    u64 r; asm("mov.b64 %0, {%1, %2};" : "=l"(r) : "r"(__float_as_uint(a)), "r"(__float_as_uint(b)));
    return r;
}
__device__ __forceinline__ void upk2(u64 v, float& a, float& b) {
    u32 x, y; asm("mov.b64 {%0, %1}, %2;" : "=r"(x), "=r"(y) : "l"(v));
    a = __uint_as_float(x); b = __uint_as_float(y);
}
__device__ __forceinline__ u64 dup2(float a) { return pk2(a, a); }
__device__ __forceinline__ u64 ffma2(u64 a, u64 b, u64 c) {
    u64 d; asm("fma.rn.f32x2 %0, %1, %2, %3;" : "=l"(d) : "l"(a), "l"(b), "l"(c)); return d;
}
__device__ __forceinline__ float2 relu2(u64 v) {
    float a, b; upk2(v, a, b); return make_float2(fmaxf(a, 0.f), fmaxf(b, 0.f));
}
__device__ __forceinline__ ulonglong2 ld128(const float* p) { return *reinterpret_cast<const ulonglong2*>(p); }
__device__ __forceinline__ u64 ld64(const float* p)         { return *reinterpret_cast<const u64*>(p); }
__device__ __forceinline__ float4 ld4(const float* p)       { return *reinterpret_cast<const float4*>(p); }
__device__ __forceinline__ void st4(float* p, float4 v)     { *reinterpret_cast<float4*>(p) = v; }
__device__ __forceinline__ float relu(float x) { return fmaxf(x, 0.f); }

__global__ __launch_bounds__(NWARP * 32)
void policy_kernel(
    const float* __restrict__ queue, const float* __restrict__ waiting,
    const float* __restrict__ phase_onehot, const float* __restrict__ elapsed,
    const int*   __restrict__ region_ids, const float* __restrict__ noise,
    const float* __restrict__ lane_w1, const float* __restrict__ lane_b1,
    const float* __restrict__ lane_w2, const float* __restrict__ lane_b2,
    const float* __restrict__ attn_in_w, const float* __restrict__ attn_in_b,
    const float* __restrict__ attn_out_w, const float* __restrict__ attn_out_b,
    const float* __restrict__ phase_w1, const float* __restrict__ phase_b1,
    const float* __restrict__ phase_w2, const float* __restrict__ phase_b2,
    const float* __restrict__ region_table,
    const float* __restrict__ head_w1, const float* __restrict__ head_b1,
    const float* __restrict__ head_w2, const float* __restrict__ head_b2,
    const float* __restrict__ log_std,
    float* __restrict__ out, int N)
{
    __shared__ float wb[NWARP][BUF];
    __shared__ float featp[200][12];

    const int tid  = threadIdx.x;
    const int warp = tid >> 5, lane = tid & 31;
    const int n0   = blockIdx.x * TLB + warp * 2;
    float* A     = wb[warp];
    float* Pp6   = &wb[0][0];
    float* Pp8a  = &wb[1][0];
    float* Pp5   = &wb[2][0];
    float* Pp8b  = &wb[2][0];
    float* phT   = &wb[3][0];
    float* obarT = &featp[64][0];

    const int rgt = lane >> 4;
    const int jg4 = (lane & 15) * 4;
    const int j4  = lane * 4;

    const int na = min(n0,     N - 1);
    const int nb = min(n0 + 1, N - 1);
    const float ee[2] = { elapsed[na], elapsed[nb] };

    // ---- S1: lane MLP L1 -> h[t*528 + l*128 + j] ----
    {
        ulonglong2 W0 = ld128(lane_w1 + j4);
        ulonglong2 W1 = ld128(lane_w1 + 128 + j4);
        ulonglong2 W2 = ld128(lane_w1 + 256 + j4);
        ulonglong2 BB = ld128(lane_b1 + j4);
#pragma unroll
        for (int t = 0; t < 2; t++) {
            const int n = t ? nb : na;
            float4 qv = ld4(queue + 4 * n);
            float4 wv = ld4(waiting + 4 * n);
            u64 ed = dup2(ee[t]);
            float qa[4] = {qv.x, qv.y, qv.z, qv.w};
            float wa[4] = {wv.x, wv.y, wv.z, wv.w};
#pragma unroll
            for (int l = 0; l < 4; l++) {
                u64 qd = dup2(qa[l]), wd = dup2(wa[l]);
                u64 lo = ffma2(qd, W0.x, BB.x); lo = ffma2(wd, W1.x, lo); lo = ffma2(ed, W2.x, lo);
                u64 hi = ffma2(qd, W0.y, BB.y); hi = ffma2(wd, W1.y, hi); hi = ffma2(ed, W2.y, hi);
                float2 r0 = relu2(lo), r1 = relu2(hi);
                st4(A + t * 528 + l * 128 + j4, make_float4(r0.x, r0.y, r1.x, r1.y));
            }
        }
    }
    __syncwarp();

    // ---- S2: lane MLP L2 -> emb[1664 + rgt*272 + l*64] ----
    {
        ulonglong2 bb = ld128(lane_b2 + jg4);
        u64 acc[4][2];
#pragma unroll
        for (int l = 0; l < 4; l++) { acc[l][0] = bb.x; acc[l][1] = bb.y; }
#pragma unroll 2
        for (int k = 0; k < 128; k += 4) {
            float hv[4][4];
#pragma unroll
            for (int l = 0; l < 4; l++) {
                float4 v = ld4(A + rgt * 528 + l * 128 + k);
                hv[l][0] = v.x; hv[l][1] = v.y; hv[l][2] = v.z; hv[l][3] = v.w;
            }
#pragma unroll
            for (int kk = 0; kk < 4; kk++) {
                ulonglong2 w = ld128(lane_w2 + (k + kk) * 64 + jg4);
#pragma unroll
                for (int l = 0; l < 4; l++) {
                    u64 d = dup2(hv[l][kk]);
                    acc[l][0] = ffma2(d, w.x, acc[l][0]);
                    acc[l][1] = ffma2(d, w.y, acc[l][1]);
                }
            }
        }
#pragma unroll
        for (int l = 0; l < 4; l++) {
            float2 r0 = relu2(acc[l][0]), r1 = relu2(acc[l][1]);
            st4(A + 1664 + rgt * 272 + l * 64 + jg4, make_float4(r0.x, r0.y, r1.x, r1.y));
        }
    }
    __syncwarp();

    // ---- S3: QKV -> qkv[t*784 + l*196 + m*64 + j]; m={0,1} share one act pass ----
    {
        ulonglong2 b0 = ld128(attn_in_b + jg4);
        ulonglong2 b1 = ld128(attn_in_b + 64 + jg4);
        u64 acc[4][2][2];   // [l][m][half]
#pragma unroll
        for (int l = 0; l < 4; l++) {
            acc[l][0][0] = b0.x; acc[l][0][1] = b0.y;
            acc[l][1][0] = b1.x; acc[l][1][1] = b1.y;
        }
#pragma unroll 2
        for (int k = 0; k < 64; k += 4) {
            float ev[4][4];
#pragma unroll
            for (int l = 0; l < 4; l++) {
                float4 v = ld4(A + 1664 + rgt * 272 + l * 64 + k);
                ev[l][0] = v.x; ev[l][1] = v.y; ev[l][2] = v.z; ev[l][3] = v.w;
            }
#pragma unroll
            for (int kk = 0; kk < 4; kk++) {
                ulonglong2 w0 = ld128(attn_in_w + (k + kk) * 192 + jg4);
                ulonglong2 w1 = ld128(attn_in_w + (k + kk) * 192 + 64 + jg4);
#pragma unroll
                for (int l = 0; l < 4; l++) {
                    u64 d = dup2(ev[l][kk]);
                    acc[l][0][0] = ffma2(d, w0.x, acc[l][0][0]);
                    acc[l][0][1] = ffma2(d, w0.y, acc[l][0][1]);
                    acc[l][1][0] = ffma2(d, w1.x, acc[l][1][0]);
                    acc[l][1][1] = ffma2(d, w1.y, acc[l][1][1]);
                }
            }
        }
#pragma unroll
        for (int l = 0; l < 4; l++)
#pragma unroll
            for (int m = 0; m < 2; m++) {
                float a0, a1, a2, a3;
                upk2(acc[l][m][0], a0, a1); upk2(acc[l][m][1], a2, a3);
                st4(A + rgt * 784 + l * 196 + m * 64 + jg4, make_float4(a0, a1, a2, a3));
            }
    }
    {   // m = 2 (V)
        ulonglong2 bm = ld128(attn_in_b + 128 + jg4);
        u64 acc[4][2];
#pragma unroll
        for (int l = 0; l < 4; l++) { acc[l][0] = bm.x; acc[l][1] = bm.y; }
#pragma unroll 2
        for (int k = 0; k < 64; k += 4) {
            float ev[4][4];
#pragma unroll
            for (int l = 0; l < 4; l++) {
                float4 v = ld4(A + 1664 + rgt * 272 + l * 64 + k);
                ev[l][0] = v.x; ev[l][1] = v.y; ev[l][2] = v.z; ev[l][3] = v.w;
            }
#pragma unroll
            for (int kk = 0; kk < 4; kk++) {
                ulonglong2 w = ld128(attn_in_w + (k + kk) * 192 + 128 + jg4);
#pragma unroll
                for (int l = 0; l < 4; l++) {
                    u64 d = dup2(ev[l][kk]);
                    acc[l][0] = ffma2(d, w.x, acc[l][0]);
                    acc[l][1] = ffma2(d, w.y, acc[l][1]);
                }
            }
        }
#pragma unroll
        for (int l = 0; l < 4; l++) {
            float a0, a1, a2, a3; upk2(acc[l][0], a0, a1); upk2(acc[l][1], a2, a3);
            st4(A + rgt * 784 + l * 196 + 128 + jg4, make_float4(a0, a1, a2, a3));
        }
    }
    __syncwarp();

    // ---- S4 fused: probs -> c_k -> obar slice -> obarT ----
    {
        const int t4 = rgt, r4 = lane & 15, hh = r4 >> 2, ql = r4 & 3;
        const float* base = A + t4 * 784;
        const float* qb = base + ql * 196 + hh * 16;
        float q[16];
#pragma unroll
        for (int i = 0; i < 4; i++) {
            float4 v = ld4(qb + 4 * i);
            q[4*i] = v.x; q[4*i+1] = v.y; q[4*i+2] = v.z; q[4*i+3] = v.w;
        }
        float sc[4];
#pragma unroll
        for (int kl = 0; kl < 4; kl++) {
            const float* kb = base + kl * 196 + 64 + hh * 16;
            float d = 0.f;
#pragma unroll
            for (int i = 0; i < 4; i++) {
                float4 v = ld4(kb + 4 * i);
                d = fmaf(q[4*i], v.x, d); d = fmaf(q[4*i+1], v.y, d);
                d = fmaf(q[4*i+2], v.z, d); d = fmaf(q[4*i+3], v.w, d);
            }
            sc[kl] = d * 0.25f;
        }
        float mx = fmaxf(fmaxf(sc[0], sc[1]), fmaxf(sc[2], sc[3]));
        float es = 0.f;
#pragma unroll
        for (int kl = 0; kl < 4; kl++) { sc[kl] = __expf(sc[kl] - mx); es += sc[kl]; }
        float inv = 1.f / es;
        float c[4];
#pragma unroll
        for (int kl = 0; kl < 4; kl++) {
            float p = sc[kl] * inv;
            p += __shfl_xor_sync(0xffffffffu, p, 1);
            p += __shfl_xor_sync(0xffffffffu, p, 2);
            c[kl] = 0.25f * p;
        }
        float4 vb = make_float4(0.f, 0.f, 0.f, 0.f);
#pragma unroll
        for (int kl = 0; kl < 4; kl++) {
            float4 v = ld4(base + kl * 196 + 128 + hh * 16 + ql * 4);
            vb.x = fmaf(c[kl], v.x, vb.x); vb.y = fmaf(c[kl], v.y, vb.y);
            vb.z = fmaf(c[kl], v.z, vb.z); vb.w = fmaf(c[kl], v.w, vb.w);
        }
        const int e0 = hh * 16 + ql * 4, col = 2 * warp + t4;
        obarT[(e0 + 0) * 12 + col] = vb.x;
        obarT[(e0 + 1) * 12 + col] = vb.y;
        obarT[(e0 + 2) * 12 + col] = vb.z;
        obarT[(e0 + 3) * 12 + col] = vb.w;
    }
    __syncthreads();

    // ==== Phase A: S5b partial (k-split) + S6L1 (transposed) ====
    {
        const int kh = warp & 1, jh = warp >> 1;
        const int j = jh * 32 + lane;
        const int k0 = kh * 32;
        u64 acc[4] = {0ULL, 0ULL, 0ULL, 0ULL};
#pragma unroll 8
        for (int k = k0; k < k0 + 32; k++) {
            u64 wd = dup2(attn_out_w[k * 64 + j]);
            ulonglong2 fa = ld128(obarT + k * 12);
            ulonglong2 fb = ld128(obarT + k * 12 + 4);
            acc[0] = ffma2(fa.x, wd, acc[0]); acc[1] = ffma2(fa.y, wd, acc[1]);
            acc[2] = ffma2(fb.x, wd, acc[2]); acc[3] = ffma2(fb.y, wd, acc[3]);
        }
#pragma unroll
        for (int rp = 0; rp < 4; rp++)
            *reinterpret_cast<u64*>(Pp5 + kh * 512 + rp * 128 + j * 2) = acc[rp];
    }
    {
        float4 poa = ld4(phase_onehot + 4 * na);
        float4 pob = ld4(phase_onehot + 4 * nb);
        float xa[5] = {poa.x, poa.y, poa.z, poa.w, ee[0]};
        float xb[5] = {pob.x, pob.y, pob.z, pob.w, ee[1]};
#pragma unroll
        for (int i = 0; i < 4; i++) {
            int h1 = lane + 32 * i;
            float b  = phase_b1[h1];
            float w0 = phase_w1[h1],       w1 = phase_w1[128 + h1], w2 = phase_w1[256 + h1];
            float w3 = phase_w1[384 + h1], w4 = phase_w1[512 + h1];
            float va = b + xa[0]*w0 + xa[1]*w1 + xa[2]*w2 + xa[3]*w3 + xa[4]*w4;
            float vb = b + xb[0]*w0 + xb[1]*w1 + xb[2]*w2 + xb[3]*w3 + xb[4]*w4;
            phT[h1 * 12 + 2 * warp + 0] = relu(va);
            phT[h1 * 12 + 2 * warp + 1] = relu(vb);
        }
    }
    __syncthreads();

    // ==== Phase B: S5b final -> featp[0:64) ; S6L2 partial ====
    {
#pragma unroll
        for (int jj2 = 0; jj2 < 2; jj2++) {
            const int jj = lane + 32 * jj2;
            u64 p0 = *reinterpret_cast<const u64*>(Pp5 + warp * 128 + jj * 2);
            u64 p1 = *reinterpret_cast<const u64*>(Pp5 + 512 + warp * 128 + jj * 2);
            float a0, a1, b0, b1; upk2(p0, a0, a1); upk2(p1, b0, b1);
            float bias = attn_out_b[jj];
            featp[jj][2 * warp + 0] = a0 + b0 + bias;
            featp[jj][2 * warp + 1] = a1 + b1 + bias;
        }
    }
    {
        const int kh = warp & 1, jh = warp >> 1;
        const int j2 = jh * 64 + lane * 2;
        const int k0 = kh * 64;
        u64 acc[8];
#pragma unroll
        for (int r = 0; r < 8; r++) acc[r] = 0ULL;
#pragma unroll 4
        for (int k = k0; k < k0 + 64; k++) {
            u64 wk = ld64(phase_w2 + k * 128 + j2);
            float4 fa = ld4(phT + k * 12);
            float4 fb = ld4(phT + k * 12 + 4);
            acc[0] = ffma2(dup2(fa.x), wk, acc[0]); acc[1] = ffma2(dup2(fa.y), wk, acc[1]);
            acc[2] = ffma2(dup2(fa.z), wk, acc[2]); acc[3] = ffma2(dup2(fa.w), wk, acc[3]);
            acc[4] = ffma2(dup2(fb.x), wk, acc[4]); acc[5] = ffma2(dup2(fb.y), wk, acc[5]);
            acc[6] = ffma2(dup2(fb.z), wk, acc[6]); acc[7] = ffma2(dup2(fb.w), wk, acc[7]);
        }
#pragma unroll
        for (int r = 0; r < 8; r++)
            *reinterpret_cast<u64*>(Pp6 + kh * 1024 + r * 128 + j2) = acc[r];
    }
    __syncthreads();

    // ==== Phase C: S6 final -> featp[64:192) ; S7 region ====
    {
        float4 b2 = ld4(phase_b2 + j4);
#pragma unroll
        for (int tt = 0; tt < 2; tt++) {
            const int r = 2 * warp + tt;
            float4 p0 = ld4(Pp6 + r * 128 + j4);
            float4 p1 = ld4(Pp6 + 1024 + r * 128 + j4);
            featp[64 + j4 + 0][r] = relu(p0.x + p1.x + b2.x);
            featp[64 + j4 + 1][r] = relu(p0.y + p1.y + b2.y);
            featp[64 + j4 + 2][r] = relu(p0.z + p1.z + b2.z);
            featp[64 + j4 + 3][r] = relu(p0.w + p1.w + b2.w);
        }
    }
    if (lane < 16) {
        const int t = lane >> 3, f = lane & 7;
        const int n = t ? nb : na;
        int rid = region_ids[n];
        rid = min(max(rid, 0), 3);
        featp[192 + f][warp * 2 + t] = region_table[rid * 8 + f];
    }
    __syncthreads();

    // ==== Phase D: S8 partial (k-half x j-half) ====
    {
        const int kh = warp & 1, jh = warp >> 1;
        const int j2 = jh * 64 + lane * 2;
        const int k0 = kh * 100;
        u64 acc[8];
#pragma unroll
        for (int r = 0; r < 8; r++) acc[r] = 0ULL;
#pragma unroll 4
        for (int k = k0; k < k0 + 100; k++) {
            u64 wk = ld64(head_w1 + k * 128 + j2);
            ulonglong2 fa = ld128(&featp[k][0]);
            ulonglong2 fb = ld128(&featp[k][4]);
            float f0, f1, f2, f3, f4, f5, f6, f7;
            upk2(fa.x, f0, f1); upk2(fa.y, f2, f3);
            upk2(fb.x, f4, f5); upk2(fb.y, f6, f7);
            acc[0] = ffma2(dup2(f0), wk, acc[0]); acc[1] = ffma2(dup2(f1), wk, acc[1]);
            acc[2] = ffma2(dup2(f2), wk, acc[2]); acc[3] = ffma2(dup2(f3), wk, acc[3]);
            acc[4] = ffma2(dup2(f4), wk, acc[4]); acc[5] = ffma2(dup2(f5), wk, acc[5]);
            acc[6] = ffma2(dup2(f6), wk, acc[6]); acc[7] = ffma2(dup2(f7), wk, acc[7]);
        }
        float* Pp8 = kh ? Pp8b : Pp8a;
#pragma unroll
        for (int r = 0; r < 8; r++)
            *reinterpret_cast<u64*>(Pp8 + r * 128 + j2) = acc[r];
    }
    __syncthreads();

    // ==== Phase E: S8 final ====
    {
        float4 b  = ld4(head_b1 + j4);
        float4 w2 = ld4(head_w2 + j4);
        float sums[2];
#pragma unroll
        for (int tt = 0; tt < 2; tt++) {
            const int r = 2 * warp + tt;
            float4 p0 = ld4(Pp8a + r * 128 + j4);
            float4 p1 = ld4(Pp8b + r * 128 + j4);
            float a0 = relu(p0.x + p1.x + b.x);
            float a1 = relu(p0.y + p1.y + b.y);
            float a2 = relu(p0.z + p1.z + b.z);
            float a3 = relu(p0.w + p1.w + b.w);
            float s = a0 * w2.x + a1 * w2.y + a2 * w2.z + a3 * w2.w;
#pragma unroll
            for (int off = 16; off > 0; off >>= 1)
                s += __shfl_xor_sync(0xffffffffu, s, off);
            sums[tt] = s;
        }
        if (lane == 0) {
            float ls = log_std[0];
            float sd = expf(ls);
            float bb2 = head_b2[0];
#pragma unroll
            for (int tt = 0; tt < 2; tt++) {
                const int n = n0 + tt;
                if (n < N) {
                    float mean = sums[tt] + bb2;
                    float nz = noise[n];
                    float act = mean + sd * nz;
                    out[n] = fminf(fmaxf(act, -1.0f), 1.0f);
                    out[N + n] = -0.5f * (nz * nz + 2.0f * ls + 1.8378770664093454f);
                }
            }
        }
    }
}

extern "C" void kernel_launch(void* const* d_in, const int* in_sizes, int n_in,
                              void* d_out, int out_size)
{
    const float* queue        = (const float*)d_in[0];
    const float* waiting      = (const float*)d_in[1];
    const float* phase_onehot = (const float*)d_in[2];
    const float* elapsed      = (const float*)d_in[3];
    const int*   region_ids   = (const int*)  d_in[4];
    const float* noise        = (const float*)d_in[5];
    const float* lane_w1      = (const float*)d_in[6];
    const float* lane_b1      = (const float*)d_in[7];
    const float* lane_w2      = (const float*)d_in[8];
    const float* lane_b2      = (const float*)d_in[9];
    const float* attn_in_w    = (const float*)d_in[10];
    const float* attn_in_b    = (const float*)d_in[11];
    const float* attn_out_w   = (const float*)d_in[12];
    const float* attn_out_b   = (const float*)d_in[13];
    const float* phase_w1     = (const float*)d_in[14];
    const float* phase_b1     = (const float*)d_in[15];
    const float* phase_w2     = (const float*)d_in[16];
    const float* phase_b2     = (const float*)d_in[17];
    const float* region_table = (const float*)d_in[18];
    const float* head_w1      = (const float*)d_in[19];
    const float* head_b1      = (const float*)d_in[20];
    const float* head_w2      = (const float*)d_in[21];
    const float* head_b2      = (const float*)d_in[22];
    const float* log_std      = (const float*)d_in[23];

    const int N = in_sizes[3];
    float* out = (float*)d_out;

    int blocks = (N + TLB - 1) / TLB;
    policy_kernel<<<blocks, NWARP * 32>>>(
        queue, waiting, phase_onehot, elapsed, region_ids, noise,
        lane_w1, lane_b1, lane_w2, lane_b2,
        attn_in_w, attn_in_b, attn_out_w, attn_out_b,
        phase_w1, phase_b1, phase_w2, phase_b2,
        region_table, head_w1, head_b1, head_w2, head_b2, log_std,
        out, N);
}